// round 11
// baseline (speedup 1.0000x reference)
#include <cuda_runtime.h>
#include <cuda_fp16.h>
#include <math.h>
#include <stdint.h>

// Problem constants (fixed for this dataset)
#define MAXN 30000
#define MAXE 480000
#define MAXNE (MAXE + MAXN)
#define HID 128
#define EPSV 1e-5f
#define DTV 0.1f
#define NSLOT 19
#define SLOT_ELEMS (128 * 128)

// ---------------- scratch (static device memory; no runtime allocs) ----------
__device__ int   g_deg[MAXN];
__device__ float g_dinv[MAXN];
__device__ int   g_rp[MAXN + 1];
__device__ int   g_cur[MAXN];
__device__ int   g_csrc[MAXNE];
__device__ float g_cw[MAXNE];
__device__ float g_stats[2 * HID];
__device__ int   g_lex[MAXN];
__device__ int   g_bsum[256];

__device__ __align__(16) __half g_h[(size_t)MAXN * HID];    // GEMM output ping
__device__ __align__(16) __half g_h2[(size_t)MAXN * HID];   // GEMM output pong
__device__ __align__(16) float g_bufA[(size_t)MAXN * HID];  // fp32 activations (IN input etc.)
__device__ __align__(16) float g_M0[(size_t)MAXN * HID];    // precomputed mesh @ W0[4:132]
__device__ __align__(16) float g_F[MAXN * 4];
__device__ __align__(16) float g_h4[MAXN * 4];

// fp16 GEMM operand buffers
__device__ __align__(16) __half g_A[(size_t)MAXN * HID];
__device__ __align__(16) __half g_B[NSLOT * SLOT_ELEMS];

// ---------------- helpers -----------------------------------------------------
__device__ __forceinline__ uint32_t smem_u32(const void* p) {
    uint32_t a;
    asm("{ .reg .u64 t; cvta.to.shared.u64 t, %1; cvt.u32.u64 %0, t; }" : "=r"(a) : "l"(p));
    return a;
}

__device__ __forceinline__ void ldmx4(uint32_t* r, uint32_t addr) {
    asm volatile("ldmatrix.sync.aligned.m8n8.x4.shared.b16 {%0,%1,%2,%3}, [%4];"
                 : "=r"(r[0]), "=r"(r[1]), "=r"(r[2]), "=r"(r[3]) : "r"(addr));
}

__device__ __forceinline__ void mma16816(float* c, const uint32_t* a, uint32_t b0, uint32_t b1) {
    asm volatile("mma.sync.aligned.m16n8k16.row.col.f32.f16.f16.f32 "
                 "{%0,%1,%2,%3}, {%4,%5,%6,%7}, {%8,%9}, {%0,%1,%2,%3};"
                 : "+f"(c[0]), "+f"(c[1]), "+f"(c[2]), "+f"(c[3])
                 : "r"(a[0]), "r"(a[1]), "r"(a[2]), "r"(a[3]), "r"(b0), "r"(b1));
}

__device__ __forceinline__ void half_store4(float4 v, __half* p) {
    __half2 h01 = __floats2half2_rn(v.x, v.y);
    __half2 h23 = __floats2half2_rn(v.z, v.w);
    uint2 pk;
    pk.x = *(uint32_t*)&h01; pk.y = *(uint32_t*)&h23;
    *(uint2*)p = pk;
}

__device__ __forceinline__ void acc_row(float4& acc, uint2 raw, float w) {
    float2 f01 = __half22float2(*(__half2*)&raw.x);
    float2 f23 = __half22float2(*(__half2*)&raw.y);
    acc.x += w * f01.x; acc.y += w * f01.y;
    acc.z += w * f23.x; acc.w += w * f23.y;
}

// full gather for one node (warp-wide, lane holds 4 channels); fp32 accum
__device__ __forceinline__ float4 gather_node(const __half* __restrict__ h,
                                              int node, int lane, float4 acc) {
    int e = g_rp[node], e1 = g_rp[node + 1];
    for (; e + 8 <= e1; e += 8) {
        int s[8]; float w[8]; uint2 r[8];
        #pragma unroll
        for (int q = 0; q < 8; q++) { s[q] = g_csrc[e + q]; w[q] = g_cw[e + q]; }
        #pragma unroll
        for (int q = 0; q < 8; q++) r[q] = ((const uint2*)(h + (size_t)s[q] * 128))[lane];
        #pragma unroll
        for (int q = 0; q < 8; q++) acc_row(acc, r[q], w[q]);
    }
    for (; e + 4 <= e1; e += 4) {
        int s[4]; float w[4]; uint2 r[4];
        #pragma unroll
        for (int q = 0; q < 4; q++) { s[q] = g_csrc[e + q]; w[q] = g_cw[e + q]; }
        #pragma unroll
        for (int q = 0; q < 4; q++) r[q] = ((const uint2*)(h + (size_t)s[q] * 128))[lane];
        #pragma unroll
        for (int q = 0; q < 4; q++) acc_row(acc, r[q], w[q]);
    }
    for (; e < e1; ++e) {
        int s = g_csrc[e]; float w = g_cw[e];
        uint2 rv = ((const uint2*)(h + (size_t)s * 128))[lane];
        acc_row(acc, rv, w);
    }
    return acc;
}

// ---------------- graph preprocessing ----------------------------------------
__global__ void k_init_deg(int n) {
    int i = blockIdx.x * blockDim.x + threadIdx.x;
    if (i < n) g_deg[i] = 1;  // self-loop
}

__global__ void k_count(const int* __restrict__ ei, int E) {
    int e = blockIdx.x * blockDim.x + threadIdx.x;
    if (e < E) atomicAdd(&g_deg[ei[E + e]], 1);
}

__global__ void k_dinv(int n) {
    int i = blockIdx.x * blockDim.x + threadIdx.x;
    if (i < n) g_dinv[i] = rsqrtf((float)g_deg[i]);
}

// multi-block exclusive scan: scan1 (local) -> scan2 (block sums) -> scan3 (add)
__global__ void k_scan1(int n) {
    __shared__ int ws[8];
    int b = blockIdx.x, t = threadIdx.x;
    int i = b * 256 + t;
    int lane = t & 31, w = t >> 5;
    int v = (i < n) ? g_deg[i] : 0;
    int x = v;
    #pragma unroll
    for (int o = 1; o < 32; o <<= 1) {
        int t2 = __shfl_up_sync(0xFFFFFFFFu, x, o);
        if (lane >= o) x += t2;
    }
    if (lane == 31) ws[w] = x;
    __syncthreads();
    if (w == 0) {
        int s = (lane < 8) ? ws[lane] : 0;
        #pragma unroll
        for (int o = 1; o < 8; o <<= 1) {
            int t2 = __shfl_up_sync(0xFFFFFFFFu, s, o);
            if (lane >= o) s += t2;
        }
        if (lane < 8) ws[lane] = s;
    }
    __syncthreads();
    int woff = (w > 0) ? ws[w - 1] : 0;
    if (i < n) g_lex[i] = woff + x - v;
    if (t == 255) g_bsum[b] = woff + x;
}

__global__ void k_scan2(int nb, int n) {
    __shared__ int ws[8];
    int t = threadIdx.x;
    int lane = t & 31, w = t >> 5;
    int v = (t < nb) ? g_bsum[t] : 0;
    int x = v;
    #pragma unroll
    for (int o = 1; o < 32; o <<= 1) {
        int t2 = __shfl_up_sync(0xFFFFFFFFu, x, o);
        if (lane >= o) x += t2;
    }
    if (lane == 31) ws[w] = x;
    __syncthreads();
    if (w == 0) {
        int s = (lane < 8) ? ws[lane] : 0;
        #pragma unroll
        for (int o = 1; o < 8; o <<= 1) {
            int t2 = __shfl_up_sync(0xFFFFFFFFu, s, o);
            if (lane >= o) s += t2;
        }
        if (lane < 8) ws[lane] = s;
    }
    __syncthreads();
    int woff = (w > 0) ? ws[w - 1] : 0;
    int excl = woff + x - v;
    __syncthreads();
    if (t < nb) g_bsum[t] = excl;
    if (t == nb - 1) g_rp[n] = woff + x;
}

__global__ void k_scan3(int n) {
    int i = blockIdx.x * blockDim.x + threadIdx.x;
    if (i < n) {
        int v = g_lex[i] + g_bsum[i >> 8];
        g_rp[i] = v;
        g_cur[i] = v;
    }
}

__global__ void k_fill(const int* __restrict__ ei, int E, int n) {
    int idx = blockIdx.x * blockDim.x + threadIdx.x;
    if (idx < E) {
        int s = ei[idx], d = ei[E + idx];
        int pos = atomicAdd(&g_cur[d], 1);
        g_csrc[pos] = s;
        g_cw[pos] = g_dinv[s] * g_dinv[d];
    } else if (idx < E + n) {
        int i = idx - E;
        int pos = atomicAdd(&g_cur[i], 1);
        g_csrc[pos] = i;
        g_cw[pos] = g_dinv[i] * g_dinv[i];
    }
}

// ---------------- weight conversion: W[KxN] fp32 -> B[NxKpad] fp16 -----------
struct WTab {
    const float* src[NSLOT];
    int K[NSLOT];
    int Kp[NSLOT];
};

__global__ void k_wconv(WTab t) {
    int slot = blockIdx.y;
    int Kp = t.Kp[slot];
    int idx = blockIdx.x * 256 + threadIdx.x;
    if (idx >= 128 * Kp) return;
    int nrow = idx / Kp, k = idx % Kp;
    float v = (k < t.K[slot]) ? t.src[slot][(size_t)k * 128 + nrow] : 0.0f;
    g_B[slot * SLOT_ELEMS + idx] = __float2half(v);
}

// meshfield [Nx8] fp32 -> fp16 [Nx16] (cols 8..15 zero)
__global__ void k_meshin(const float* __restrict__ mf, int n) {
    int idx = blockIdx.x * blockDim.x + threadIdx.x;
    if (idx >= n * 16) return;
    int node = idx >> 4, c = idx & 15;
    float v = (c < 8) ? mf[node * 8 + c] : 0.0f;
    g_A[idx] = __float2half(v);
}

// ---------------- shared GEMM geometry ----------------------------------------
#define SMS 136                         // smem row stride in halves (128 + 8 pad)
#define SM_A 0
#define SM_B (128 * SMS * 2)            // 34816
#define GEMM_SMEM (SM_B + 128 * SMS * 2)  // 69632 bytes

// ---------------- mma.sync fp16 GEMM, M-tile 128 -------------------------------
__global__ __launch_bounds__(256) void k_mmagemm(
    const __half* __restrict__ A, const __half* __restrict__ B,
    void* __restrict__ outp, int n, int K, int out_half)
{
    extern __shared__ __align__(16) char smem[];
    int tid = threadIdx.x;
    int m0 = blockIdx.x * 128;
    int nb8 = K >> 3;

    for (int idx = tid; idx < 128 * nb8; idx += 256) {
        int r = idx / nb8, c = idx - r * nb8;
        uint4 v = *(const uint4*)(B + (size_t)r * K + c * 8);
        *(uint4*)(smem + SM_B + (r * SMS + c * 8) * 2) = v;
    }
    for (int idx = tid; idx < 128 * nb8; idx += 256) {
        int r = idx / nb8, c = idx - r * nb8;
        int gr = m0 + r;
        uint4 v = make_uint4(0, 0, 0, 0);
        if (gr < n) v = *(const uint4*)(A + (size_t)gr * K + c * 8);
        *(uint4*)(smem + SM_A + (r * SMS + c * 8) * 2) = v;
    }
    __syncthreads();

    uint32_t sb = smem_u32(smem);
    int wid = tid >> 5, lane = tid & 31;
    int rowbase = wid * 16;

    int a_row  = (lane & 7) + ((lane >> 3) & 1) * 8;
    int a_koff = (lane >> 4) * 8;
    int b_nrow = ((lane >> 4) * 8) + (lane & 7);
    int b_koff = ((lane >> 3) & 1) * 8;

    float acc[16][4];
    #pragma unroll
    for (int j = 0; j < 16; j++)
        #pragma unroll
        for (int q = 0; q < 4; q++) acc[j][q] = 0.f;

    int ksteps = K >> 4;
    for (int ks = 0; ks < ksteps; ks++) {
        uint32_t a0[4];
        uint32_t aaddr = sb + SM_A + (uint32_t)(((rowbase + a_row) * SMS + a_koff + ks * 16) * 2);
        ldmx4(a0, aaddr);
        #pragma unroll
        for (int p = 0; p < 8; p++) {
            uint32_t b[4];
            uint32_t baddr = sb + SM_B + (uint32_t)(((p * 16 + b_nrow) * SMS + b_koff + ks * 16) * 2);
            ldmx4(b, baddr);
            mma16816(acc[2 * p + 0], a0, b[0], b[1]);
            mma16816(acc[2 * p + 1], a0, b[2], b[3]);
        }
    }

    int g = lane >> 2, i4 = lane & 3;
    int r0 = m0 + rowbase + g;
    if (out_half) {
        __half* out = (__half*)outp;
        #pragma unroll
        for (int nt = 0; nt < 16; nt++) {
            int col = nt * 8 + i4 * 2;
            if (r0 < n)
                *(__half2*)(out + (size_t)r0 * 128 + col) =
                    __floats2half2_rn(acc[nt][0], acc[nt][1]);
            if (r0 + 8 < n)
                *(__half2*)(out + (size_t)(r0 + 8) * 128 + col) =
                    __floats2half2_rn(acc[nt][2], acc[nt][3]);
        }
    } else {
        float* out = (float*)outp;
        #pragma unroll
        for (int nt = 0; nt < 16; nt++) {
            int col = nt * 8 + i4 * 2;
            if (r0 < n)
                *(float2*)(out + (size_t)r0 * 128 + col) = make_float2(acc[nt][0], acc[nt][1]);
            if (r0 + 8 < n)
                *(float2*)(out + (size_t)(r0 + 8) * 128 + col) = make_float2(acc[nt][2], acc[nt][3]);
        }
    }
}

// ---------------- FUSED conv: x = act(agg(h_in)+b); h_out = x @ W^T ------------
// act: 1 = relu, 0 = none. Aggregation accumulates fp32, x stored fp16 in smem A.
__global__ __launch_bounds__(256) void k_fusedconv(
    const __half* __restrict__ h_in, const float* __restrict__ bias,
    const __half* __restrict__ W, __half* __restrict__ h_out,
    int n, int act)
{
    extern __shared__ __align__(16) char smem[];
    int tid = threadIdx.x;
    int m0 = blockIdx.x * 128;
    int wid = tid >> 5, lane = tid & 31;

    // stage B tile (128 x 128 fp16)
    for (int idx = tid; idx < 128 * 16; idx += 256) {
        int r = idx >> 4, c = idx & 15;
        uint4 v = *(const uint4*)(W + (size_t)r * 128 + c * 8);
        *(uint4*)(smem + SM_B + (r * SMS + c * 8) * 2) = v;
    }

    // aggregation phase: each warp produces 16 rows of the A tile
    float4 bv = ((const float4*)bias)[lane];
    for (int i = 0; i < 16; i++) {
        int node = m0 + wid * 16 + i;
        float4 acc = make_float4(0.f, 0.f, 0.f, 0.f);
        if (node < n) {
            acc = gather_node(h_in, node, lane, bv);
            if (act) {
                acc.x = fmaxf(acc.x, 0.f); acc.y = fmaxf(acc.y, 0.f);
                acc.z = fmaxf(acc.z, 0.f); acc.w = fmaxf(acc.w, 0.f);
            }
        }
        __half2 h01 = __floats2half2_rn(acc.x, acc.y);
        __half2 h23 = __floats2half2_rn(acc.z, acc.w);
        uint2 pk;
        pk.x = *(uint32_t*)&h01; pk.y = *(uint32_t*)&h23;
        *(uint2*)(smem + SM_A + ((wid * 16 + i) * SMS + lane * 4) * 2) = pk;
    }
    __syncthreads();

    // MMA phase
    uint32_t sb = smem_u32(smem);
    int rowbase = wid * 16;
    int a_row  = (lane & 7) + ((lane >> 3) & 1) * 8;
    int a_koff = (lane >> 4) * 8;
    int b_nrow = ((lane >> 4) * 8) + (lane & 7);
    int b_koff = ((lane >> 3) & 1) * 8;

    float acc[16][4];
    #pragma unroll
    for (int j = 0; j < 16; j++)
        #pragma unroll
        for (int q = 0; q < 4; q++) acc[j][q] = 0.f;

    for (int ks = 0; ks < 8; ks++) {
        uint32_t a0[4];
        uint32_t aaddr = sb + SM_A + (uint32_t)(((rowbase + a_row) * SMS + a_koff + ks * 16) * 2);
        ldmx4(a0, aaddr);
        #pragma unroll
        for (int p = 0; p < 8; p++) {
            uint32_t b[4];
            uint32_t baddr = sb + SM_B + (uint32_t)(((p * 16 + b_nrow) * SMS + b_koff + ks * 16) * 2);
            ldmx4(b, baddr);
            mma16816(acc[2 * p + 0], a0, b[0], b[1]);
            mma16816(acc[2 * p + 1], a0, b[2], b[3]);
        }
    }

    int g = lane >> 2, i4 = lane & 3;
    int r0 = m0 + rowbase + g;
    #pragma unroll
    for (int nt = 0; nt < 16; nt++) {
        int col = nt * 8 + i4 * 2;
        if (r0 < n)
            *(__half2*)(h_out + (size_t)r0 * 128 + col) =
                __floats2half2_rn(acc[nt][0], acc[nt][1]);
        if (r0 + 8 < n)
            *(__half2*)(h_out + (size_t)(r0 + 8) * 128 + col) =
                __floats2half2_rn(acc[nt][2], acc[nt][3]);
    }
}

// ---------------- standalone aggregation (mode 0 fp32+stats-zero, mode 3 tanh) -
__global__ __launch_bounds__(256) void k_agg128(
    const __half* __restrict__ h, const float* __restrict__ bias,
    float* __restrict__ outF, __half* __restrict__ outHalf,
    int n, int mode)
{
    if (mode == 0 && blockIdx.x == 0) g_stats[threadIdx.x] = 0.f;  // fold zero_stats
    int node = blockIdx.x * 8 + (threadIdx.x >> 5);
    if (node >= n) return;
    int lane = threadIdx.x & 31;
    float4 acc = gather_node(h, node, lane, ((const float4*)bias)[lane]);
    if (mode == 0) {
        ((float4*)(outF + (size_t)node * 128))[lane] = acc;
    } else {
        acc.x = tanhf(acc.x); acc.y = tanhf(acc.y);
        acc.z = tanhf(acc.z); acc.w = tanhf(acc.w);
        half_store4(acc, outHalf + (size_t)node * 128 + lane * 4);
    }
}

// ---------------- instance norm ----------------------------------------------
__global__ __launch_bounds__(128) void k_in_stats(const float* __restrict__ x, int n) {
    int c = threadIdx.x;
    int chunk = (n + gridDim.x - 1) / gridDim.x;
    int r0 = blockIdx.x * chunk;
    int r1 = min(n, r0 + chunk);
    float s = 0.f, q = 0.f;
    for (int r = r0; r < r1; ++r) {
        float v = x[(size_t)r * HID + c];
        s += v; q += v * v;
    }
    atomicAdd(&g_stats[c], s);
    atomicAdd(&g_stats[HID + c], q);
}

// apply IN, then ReLU, write fp16 (feeds first middle conv)
__global__ void k_in_apply_half(const float* __restrict__ x, int n) {
    int idx = blockIdx.x * blockDim.x + threadIdx.x;
    if (idx >= n * HID) return;
    int c = idx & (HID - 1);
    float inv_n = 1.f / (float)n;
    float m = g_stats[c] * inv_n;
    float v = g_stats[HID + c] * inv_n - m * m;
    float y = (x[idx] - m) * rsqrtf(v + EPSV);
    y = fmaxf(y, 0.f);
    g_A[idx] = __float2half(y);
}

// ---------------- misc small kernels ------------------------------------------
__global__ void k_copyF0(const float* __restrict__ F0, int n) {
    int i = blockIdx.x * blockDim.x + threadIdx.x;
    if (i < n) ((float4*)g_F)[i] = ((const float4*)F0)[i];
}

// h = F @ W0[0:4] + M0   (diff conv0, mesh part precomputed), fp16 out
__global__ __launch_bounds__(256) void k_conv0_diff(const float* __restrict__ W0, int n) {
    int node = blockIdx.x * 8 + (threadIdx.x >> 5);
    if (node >= n) return;
    int lane = threadIdx.x & 31;
    float4 Fv = ((const float4*)g_F)[node];
    float4 m = ((const float4*)(g_M0 + (size_t)node * 128))[lane];
    const float4* w = (const float4*)W0;
    float4 w0 = w[0 * 32 + lane], w1 = w[1 * 32 + lane];
    float4 w2 = w[2 * 32 + lane], w3 = w[3 * 32 + lane];
    m.x += Fv.x * w0.x + Fv.y * w1.x + Fv.z * w2.x + Fv.w * w3.x;
    m.y += Fv.x * w0.y + Fv.y * w1.y + Fv.z * w2.y + Fv.w * w3.y;
    m.z += Fv.x * w0.z + Fv.y * w1.z + Fv.z * w2.z + Fv.w * w3.z;
    m.w += Fv.x * w0.w + Fv.y * w1.w + Fv.z * w2.w + Fv.w * w3.w;
    half_store4(m, g_h + (size_t)node * 128 + lane * 4);
}

// out[n][4] = x[n][128] @ W[128][4]
__global__ __launch_bounds__(256) void k_gemm_h4(
    const float* __restrict__ x, const float* __restrict__ W,
    float* __restrict__ out, int n)
{
    int warp = blockIdx.x * 8 + (threadIdx.x >> 5);
    if (warp >= n) return;
    int lane = threadIdx.x & 31;
    float4 xv = ((const float4*)(x + (size_t)warp * HID))[lane];
    const float4* Wv = (const float4*)W;
    float4 w0 = Wv[lane * 4 + 0], w1 = Wv[lane * 4 + 1];
    float4 w2 = Wv[lane * 4 + 2], w3 = Wv[lane * 4 + 3];
    float4 p;
    p.x = xv.x * w0.x + xv.y * w1.x + xv.z * w2.x + xv.w * w3.x;
    p.y = xv.x * w0.y + xv.y * w1.y + xv.z * w2.y + xv.w * w3.y;
    p.z = xv.x * w0.z + xv.y * w1.z + xv.z * w2.z + xv.w * w3.z;
    p.w = xv.x * w0.w + xv.y * w1.w + xv.z * w2.w + xv.w * w3.w;
    #pragma unroll
    for (int o = 16; o > 0; o >>= 1) {
        p.x += __shfl_xor_sync(0xFFFFFFFFu, p.x, o);
        p.y += __shfl_xor_sync(0xFFFFFFFFu, p.y, o);
        p.z += __shfl_xor_sync(0xFFFFFFFFu, p.z, o);
        p.w += __shfl_xor_sync(0xFFFFFFFFu, p.w, o);
    }
    if (lane == 0) ((float4*)out)[warp] = p;
}

// fused: 4-channel aggregation + bias + tanh -> F_dot; F update; write outputs
__global__ void k_agg4_step(const float* __restrict__ h4, const float* __restrict__ b,
                            float* __restrict__ out, int n, int T, int t)
{
    int i = blockIdx.x * blockDim.x + threadIdx.x;
    if (i >= n) return;
    float4 acc = *(const float4*)b;
    int e0 = g_rp[i], e1 = g_rp[i + 1];
    for (int e = e0; e < e1; ++e) {
        int s = g_csrc[e]; float w = g_cw[e];
        float4 hv = ((const float4*)h4)[s];
        acc.x += w * hv.x; acc.y += w * hv.y; acc.z += w * hv.z; acc.w += w * hv.w;
    }
    float4 fd;
    fd.x = tanhf(acc.x); fd.y = tanhf(acc.y);
    fd.z = tanhf(acc.z); fd.w = tanhf(acc.w);
    float4 fc = ((const float4*)g_F)[i];
    float4 fn;
    fn.x = tanhf(fc.x + fd.x * DTV);
    fn.y = tanhf(fc.y + fd.y * DTV);
    fn.z = tanhf(fc.z + fd.z * DTV);
    fn.w = tanhf(fc.w + fd.w * DTV);
    ((float4*)g_F)[i] = fn;
    float4* ob = (float4*)out;
    ob[(size_t)i * T + t] = fn;                     // Fs     [N][T][4]
    ob[(size_t)n * T + (size_t)i * T + t] = fd;     // F_dots [N][T][4]
}

// ---------------- host orchestration ------------------------------------------
extern "C" void kernel_launch(void* const* d_in, const int* in_sizes, int n_in,
                              void* d_out, int out_size)
{
    const float* F0    = (const float*)d_in[0];
    const int*   ei    = (const int*)d_in[1];
    const float* meshf = (const float*)d_in[2];
    const float* mW0   = (const float*)d_in[4];
    const float* mb0   = (const float*)d_in[5];
    const float* mWh   = (const float*)d_in[6];
    const float* mbh   = (const float*)d_in[7];
    const float* mW9   = (const float*)d_in[8];
    const float* mb9   = (const float*)d_in[9];
    const float* dW0   = (const float*)d_in[10];
    const float* db0   = (const float*)d_in[11];
    const float* dWh   = (const float*)d_in[12];
    const float* dbh   = (const float*)d_in[13];
    const float* dW9   = (const float*)d_in[14];
    const float* db9   = (const float*)d_in[15];
    float* out = (float*)d_out;

    int N = in_sizes[0] / 4;
    int E = in_sizes[1] / 2;
    int T = out_size / (2 * N * 4);
    if (N > MAXN || E > MAXE || T <= 0) return;

    float *bufA, *M0buf, *h4;
    __half *hbuf, *h2buf, *Abuf, *Bbuf;
    cudaGetSymbolAddress((void**)&hbuf,  g_h);
    cudaGetSymbolAddress((void**)&h2buf, g_h2);
    cudaGetSymbolAddress((void**)&bufA,  g_bufA);
    cudaGetSymbolAddress((void**)&M0buf, g_M0);
    cudaGetSymbolAddress((void**)&h4,    g_h4);
    cudaGetSymbolAddress((void**)&Abuf,  g_A);
    cudaGetSymbolAddress((void**)&Bbuf,  g_B);

    cudaFuncSetAttribute(k_mmagemm,  cudaFuncAttributeMaxDynamicSharedMemorySize, GEMM_SMEM);
    cudaFuncSetAttribute(k_fusedconv, cudaFuncAttributeMaxDynamicSharedMemorySize, GEMM_SMEM);

    int gN = (N + 255) / 256;
    int gE = (E + 255) / 256;
    int gMM = (N + 127) / 128;   // M-tiles of 128 (GEMM + fused)
    int gA = (N + 7) / 8;
    int nb = (N + 255) / 256;

    // ---- graph preprocessing ----
    k_init_deg<<<gN, 256>>>(N);
    k_count<<<gE, 256>>>(ei, E);
    k_dinv<<<gN, 256>>>(N);
    k_scan1<<<nb, 256>>>(N);
    k_scan2<<<1, 256>>>(nb, N);
    k_scan3<<<gN, 256>>>(N);
    k_fill<<<(E + N + 255) / 256, 256>>>(ei, E, N);

    // ---- weight conversion (all 19 slots in one launch) ----
    WTab wt;
    wt.src[0] = mW0;  wt.K[0] = 8;   wt.Kp[0] = 16;            // mesh conv0
    for (int l = 0; l < 8; ++l) { wt.src[1 + l] = mWh + (size_t)l * HID * HID; wt.K[1 + l] = 128; wt.Kp[1 + l] = 128; }
    wt.src[9] = mW9;  wt.K[9] = 128; wt.Kp[9] = 128;           // mesh conv9
    for (int l = 0; l < 8; ++l) { wt.src[10 + l] = dWh + (size_t)l * HID * HID; wt.K[10 + l] = 128; wt.Kp[10 + l] = 128; }
    wt.src[18] = dW0 + 4 * HID; wt.K[18] = 128; wt.Kp[18] = 128;  // diff W0 mesh rows 4..131
    k_wconv<<<dim3(64, NSLOT), 256>>>(wt);

    // ---- mesh descriptor block ----
    k_meshin<<<(N * 16 + 255) / 256, 256>>>(meshf, N);
    k_mmagemm<<<gMM, 256, GEMM_SMEM>>>(Abuf, Bbuf, hbuf, N, 16, 1);        // conv0
    k_agg128<<<gA, 256>>>(hbuf, mb0, bufA, Abuf, N, 0);                    // + zero stats
    k_in_stats<<<512, 128>>>(bufA, N);
    k_in_apply_half<<<(N * HID + 255) / 256, 256>>>(bufA, N);              // -> g_A
    k_mmagemm<<<gMM, 256, GEMM_SMEM>>>(Abuf, Bbuf + (size_t)1 * SLOT_ELEMS, hbuf, N, 128, 1);
    {
        __half* cur = hbuf; __half* nxt = h2buf;
        for (int l = 1; l < 8; ++l) {   // fused: agg(b_{l-1}) + relu + GEMM W_l
            k_fusedconv<<<gMM, 256, GEMM_SMEM>>>(cur, mbh + (size_t)(l - 1) * HID,
                Bbuf + (size_t)(1 + l) * SLOT_ELEMS, nxt, N, 1);
            __half* tmp = cur; cur = nxt; nxt = tmp;
        }
        // fused conv9: agg(b_7, no act) + GEMM W9
        k_fusedconv<<<gMM, 256, GEMM_SMEM>>>(cur, mbh + (size_t)7 * HID,
            Bbuf + (size_t)9 * SLOT_ELEMS, nxt, N, 0);
        k_agg128<<<gA, 256>>>(nxt, mb9, bufA, Abuf, N, 3);                 // tanh -> mesh fp16
    }

    // ---- precompute M0 = mesh @ dW0[4:132]  (time-invariant, fp32) ----
    k_mmagemm<<<gMM, 256, GEMM_SMEM>>>(Abuf,
        Bbuf + (size_t)18 * SLOT_ELEMS, M0buf, N, 128, 0);

    // ---- time stepping ----
    k_copyF0<<<gN, 256>>>(F0, N);
    for (int t = 0; t < T; ++t) {
        k_conv0_diff<<<gA, 256>>>(dW0, N);                                 // -> g_h
        k_agg128<<<gA, 256>>>(hbuf, db0, bufA, Abuf, N, 0);                // + zero stats
        k_in_stats<<<512, 128>>>(bufA, N);
        k_in_apply_half<<<(N * HID + 255) / 256, 256>>>(bufA, N);          // -> g_A
        k_mmagemm<<<gMM, 256, GEMM_SMEM>>>(Abuf,
            Bbuf + (size_t)10 * SLOT_ELEMS, hbuf, N, 128, 1);              // W_h0
        __half* cur = hbuf; __half* nxt = h2buf;
        for (int l = 1; l < 8; ++l) {   // fused: agg(b_{l-1}) + relu + GEMM W_l
            k_fusedconv<<<gMM, 256, GEMM_SMEM>>>(cur, dbh + (size_t)(l - 1) * HID,
                Bbuf + (size_t)(10 + l) * SLOT_ELEMS, nxt, N, 1);
            __half* tmp = cur; cur = nxt; nxt = tmp;
        }
        k_agg128<<<gA, 256>>>(cur, dbh + (size_t)7 * HID, bufA, Abuf, N, 0);  // -> bufA fp32
        k_gemm_h4<<<gA, 256>>>(bufA, dW9, h4, N);
        k_agg4_step<<<gN, 256>>>(h4, db9, out, N, T, t);
    }
}

// round 13
// speedup vs baseline: 1.1411x; 1.1411x over previous
#include <cuda_runtime.h>
#include <cuda_fp16.h>
#include <math.h>
#include <stdint.h>

// Problem constants (fixed for this dataset)
#define MAXN 30000
#define MAXE 480000
#define MAXNE (MAXE + MAXN)
#define HID 128
#define EPSV 1e-5f
#define DTV 0.1f
#define NSLOT 19
#define SLOT_ELEMS (128 * 128)

// ---------------- scratch (static device memory; no runtime allocs) ----------
__device__ int   g_deg[MAXN];
__device__ float g_dinv[MAXN];
__device__ int   g_rp[MAXN + 1];
__device__ int   g_cur[MAXN];
__device__ int   g_csrc[MAXNE];
__device__ float g_cw[MAXNE];
__device__ float g_stats[2 * HID];
__device__ int   g_lex[MAXN];
__device__ int   g_bsum[256];

__device__ __align__(16) __half g_h[(size_t)MAXN * HID];    // GEMM output (pre-aggregation), fp16
__device__ __align__(16) float g_bufA[(size_t)MAXN * HID];  // fp32 activations (IN input)
__device__ __align__(16) float g_M0[(size_t)MAXN * HID];    // precomputed mesh @ W0[4:132]
__device__ __align__(16) float g_F[MAXN * 4];
__device__ __align__(16) float g_h4[MAXN * 4];

// fp16 GEMM operand buffers
__device__ __align__(16) __half g_A[(size_t)MAXN * HID];
__device__ __align__(16) __half g_B[NSLOT * SLOT_ELEMS];

// ---------------- helpers -----------------------------------------------------
__device__ __forceinline__ uint32_t smem_u32(const void* p) {
    uint32_t a;
    asm("{ .reg .u64 t; cvta.to.shared.u64 t, %1; cvt.u32.u64 %0, t; }" : "=r"(a) : "l"(p));
    return a;
}

__device__ __forceinline__ void ldmx4(uint32_t* r, uint32_t addr) {
    asm volatile("ldmatrix.sync.aligned.m8n8.x4.shared.b16 {%0,%1,%2,%3}, [%4];"
                 : "=r"(r[0]), "=r"(r[1]), "=r"(r[2]), "=r"(r[3]) : "r"(addr));
}

__device__ __forceinline__ void mma16816(float* c, const uint32_t* a, uint32_t b0, uint32_t b1) {
    asm volatile("mma.sync.aligned.m16n8k16.row.col.f32.f16.f16.f32 "
                 "{%0,%1,%2,%3}, {%4,%5,%6,%7}, {%8,%9}, {%0,%1,%2,%3};"
                 : "+f"(c[0]), "+f"(c[1]), "+f"(c[2]), "+f"(c[3])
                 : "r"(a[0]), "r"(a[1]), "r"(a[2]), "r"(a[3]), "r"(b0), "r"(b1));
}

__device__ __forceinline__ void half_store4(float4 v, __half* p) {
    __half2 h01 = __floats2half2_rn(v.x, v.y);
    __half2 h23 = __floats2half2_rn(v.z, v.w);
    uint2 pk;
    pk.x = *(uint32_t*)&h01; pk.y = *(uint32_t*)&h23;
    *(uint2*)p = pk;
}

__device__ __forceinline__ void acc_row(float4& acc, uint2 raw, float w) {
    float2 f01 = __half22float2(*(__half2*)&raw.x);
    float2 f23 = __half22float2(*(__half2*)&raw.y);
    acc.x += w * f01.x; acc.y += w * f01.y;
    acc.z += w * f23.x; acc.w += w * f23.y;
}

// ---------------- graph preprocessing ----------------------------------------
__global__ void k_init_deg(int n) {
    int i = blockIdx.x * blockDim.x + threadIdx.x;
    if (i < n) g_deg[i] = 1;  // self-loop
}

__global__ void k_count(const int* __restrict__ ei, int E) {
    int e = blockIdx.x * blockDim.x + threadIdx.x;
    if (e < E) atomicAdd(&g_deg[ei[E + e]], 1);
}

__global__ void k_dinv(int n) {
    int i = blockIdx.x * blockDim.x + threadIdx.x;
    if (i < n) g_dinv[i] = rsqrtf((float)g_deg[i]);
}

// multi-block exclusive scan: scan1 (local) -> scan2 (block sums) -> scan3 (add)
__global__ void k_scan1(int n) {
    __shared__ int ws[8];
    int b = blockIdx.x, t = threadIdx.x;
    int i = b * 256 + t;
    int lane = t & 31, w = t >> 5;
    int v = (i < n) ? g_deg[i] : 0;
    int x = v;
    #pragma unroll
    for (int o = 1; o < 32; o <<= 1) {
        int t2 = __shfl_up_sync(0xFFFFFFFFu, x, o);
        if (lane >= o) x += t2;
    }
    if (lane == 31) ws[w] = x;
    __syncthreads();
    if (w == 0) {
        int s = (lane < 8) ? ws[lane] : 0;
        #pragma unroll
        for (int o = 1; o < 8; o <<= 1) {
            int t2 = __shfl_up_sync(0xFFFFFFFFu, s, o);
            if (lane >= o) s += t2;
        }
        if (lane < 8) ws[lane] = s;
    }
    __syncthreads();
    int woff = (w > 0) ? ws[w - 1] : 0;
    if (i < n) g_lex[i] = woff + x - v;
    if (t == 255) g_bsum[b] = woff + x;
}

__global__ void k_scan2(int nb, int n) {
    __shared__ int ws[8];
    int t = threadIdx.x;
    int lane = t & 31, w = t >> 5;
    int v = (t < nb) ? g_bsum[t] : 0;
    int x = v;
    #pragma unroll
    for (int o = 1; o < 32; o <<= 1) {
        int t2 = __shfl_up_sync(0xFFFFFFFFu, x, o);
        if (lane >= o) x += t2;
    }
    if (lane == 31) ws[w] = x;
    __syncthreads();
    if (w == 0) {
        int s = (lane < 8) ? ws[lane] : 0;
        #pragma unroll
        for (int o = 1; o < 8; o <<= 1) {
            int t2 = __shfl_up_sync(0xFFFFFFFFu, s, o);
            if (lane >= o) s += t2;
        }
        if (lane < 8) ws[lane] = s;
    }
    __syncthreads();
    int woff = (w > 0) ? ws[w - 1] : 0;
    int excl = woff + x - v;
    __syncthreads();
    if (t < nb) g_bsum[t] = excl;
    if (t == nb - 1) g_rp[n] = woff + x;
}

__global__ void k_scan3(int n) {
    int i = blockIdx.x * blockDim.x + threadIdx.x;
    if (i < n) {
        int v = g_lex[i] + g_bsum[i >> 8];
        g_rp[i] = v;
        g_cur[i] = v;
    }
}

__global__ void k_fill(const int* __restrict__ ei, int E, int n) {
    int idx = blockIdx.x * blockDim.x + threadIdx.x;
    if (idx < E) {
        int s = ei[idx], d = ei[E + idx];
        int pos = atomicAdd(&g_cur[d], 1);
        g_csrc[pos] = s;
        g_cw[pos] = g_dinv[s] * g_dinv[d];
    } else if (idx < E + n) {
        int i = idx - E;
        int pos = atomicAdd(&g_cur[i], 1);
        g_csrc[pos] = i;
        g_cw[pos] = g_dinv[i] * g_dinv[i];
    }
}

// ---------------- weight conversion: W[KxN] fp32 -> B[NxKpad] fp16 -----------
struct WTab {
    const float* src[NSLOT];
    int K[NSLOT];
    int Kp[NSLOT];
};

__global__ void k_wconv(WTab t) {
    int slot = blockIdx.y;
    int Kp = t.Kp[slot];
    int idx = blockIdx.x * 256 + threadIdx.x;
    if (idx >= 128 * Kp) return;
    int nrow = idx / Kp, k = idx % Kp;
    float v = (k < t.K[slot]) ? t.src[slot][(size_t)k * 128 + nrow] : 0.0f;
    g_B[slot * SLOT_ELEMS + idx] = __float2half(v);
}

// meshfield [Nx8] fp32 -> fp16 [Nx16] (cols 8..15 zero); also zero g_stats
__global__ void k_meshin(const float* __restrict__ mf, int n) {
    int idx = blockIdx.x * blockDim.x + threadIdx.x;
    if (blockIdx.x == 0 && threadIdx.x < 256) g_stats[threadIdx.x] = 0.f;
    if (idx >= n * 16) return;
    int node = idx >> 4, c = idx & 15;
    float v = (c < 8) ? mf[node * 8 + c] : 0.0f;
    g_A[idx] = __float2half(v);
}

// ---------------- mma.sync fp16 GEMM, M-tile 128 ------------------------------
#define SMS 136                         // smem row stride in halves (128 + 8 pad)
#define SM_A 0
#define SM_B (128 * SMS * 2)            // 34816
#define GEMM_SMEM (SM_B + 128 * SMS * 2)  // 69632 bytes

__global__ __launch_bounds__(256) void k_mmagemm(
    const __half* __restrict__ A, const __half* __restrict__ B,
    void* __restrict__ outp, int n, int K, int out_half)
{
    extern __shared__ __align__(16) char smem[];
    int tid = threadIdx.x;
    int m0 = blockIdx.x * 128;
    int nb8 = K >> 3;

    for (int idx = tid; idx < 128 * nb8; idx += 256) {
        int r = idx / nb8, c = idx - r * nb8;
        uint4 v = *(const uint4*)(B + (size_t)r * K + c * 8);
        *(uint4*)(smem + SM_B + (r * SMS + c * 8) * 2) = v;
    }
    for (int idx = tid; idx < 128 * nb8; idx += 256) {
        int r = idx / nb8, c = idx - r * nb8;
        int gr = m0 + r;
        uint4 v = make_uint4(0, 0, 0, 0);
        if (gr < n) v = *(const uint4*)(A + (size_t)gr * K + c * 8);
        *(uint4*)(smem + SM_A + (r * SMS + c * 8) * 2) = v;
    }
    __syncthreads();

    uint32_t sb = smem_u32(smem);
    int wid = tid >> 5, lane = tid & 31;
    int rowbase = wid * 16;

    int a_row  = (lane & 7) + ((lane >> 3) & 1) * 8;
    int a_koff = (lane >> 4) * 8;
    int b_nrow = ((lane >> 4) * 8) + (lane & 7);
    int b_koff = ((lane >> 3) & 1) * 8;

    float acc[16][4];
    #pragma unroll
    for (int j = 0; j < 16; j++)
        #pragma unroll
        for (int q = 0; q < 4; q++) acc[j][q] = 0.f;

    int ksteps = K >> 4;
    for (int ks = 0; ks < ksteps; ks++) {
        uint32_t a0[4];
        uint32_t aaddr = sb + SM_A + (uint32_t)(((rowbase + a_row) * SMS + a_koff + ks * 16) * 2);
        ldmx4(a0, aaddr);
        #pragma unroll
        for (int p = 0; p < 8; p++) {
            uint32_t b[4];
            uint32_t baddr = sb + SM_B + (uint32_t)(((p * 16 + b_nrow) * SMS + b_koff + ks * 16) * 2);
            ldmx4(b, baddr);
            mma16816(acc[2 * p + 0], a0, b[0], b[1]);
            mma16816(acc[2 * p + 1], a0, b[2], b[3]);
        }
    }

    int g = lane >> 2, i4 = lane & 3;
    int r0 = m0 + rowbase + g;
    if (out_half) {
        __half* out = (__half*)outp;
        #pragma unroll
        for (int nt = 0; nt < 16; nt++) {
            int col = nt * 8 + i4 * 2;
            if (r0 < n)
                *(__half2*)(out + (size_t)r0 * 128 + col) =
                    __floats2half2_rn(acc[nt][0], acc[nt][1]);
            if (r0 + 8 < n)
                *(__half2*)(out + (size_t)(r0 + 8) * 128 + col) =
                    __floats2half2_rn(acc[nt][2], acc[nt][3]);
        }
    } else {
        float* out = (float*)outp;
        #pragma unroll
        for (int nt = 0; nt < 16; nt++) {
            int col = nt * 8 + i4 * 2;
            if (r0 < n)
                *(float2*)(out + (size_t)r0 * 128 + col) = make_float2(acc[nt][0], acc[nt][1]);
            if (r0 + 8 < n)
                *(float2*)(out + (size_t)(r0 + 8) * 128 + col) = make_float2(acc[nt][2], acc[nt][3]);
        }
    }
}

// ---------------- GEMM with fused IN-apply + ReLU prologue --------------------
// A-staging reads bufA fp32, normalizes with g_stats, relu, fp16 into smem.
// K fixed = 128. Output fp16 h.
__global__ __launch_bounds__(256) void k_mmagemm_in(
    const float* __restrict__ Af, const __half* __restrict__ B,
    __half* __restrict__ outh, int n, float inv_n)
{
    extern __shared__ __align__(16) char smem[];
    int tid = threadIdx.x;
    int m0 = blockIdx.x * 128;

    for (int idx = tid; idx < 128 * 16; idx += 256) {
        int r = idx >> 4, c = idx & 15;
        uint4 v = *(const uint4*)(B + (size_t)r * 128 + c * 8);
        *(uint4*)(smem + SM_B + (r * SMS + c * 8) * 2) = v;
    }
    for (int idx = tid; idx < 128 * 16; idx += 256) {
        int r = idx >> 4, c = idx & 15;
        int gr = m0 + r;
        int c0 = c * 8;
        float y[8];
        #pragma unroll
        for (int j = 0; j < 8; j++) {
            float mcol = g_stats[c0 + j] * inv_n;
            float vcol = g_stats[128 + c0 + j] * inv_n - mcol * mcol;
            float sc = rsqrtf(vcol + EPSV);
            float xv = (gr < n) ? Af[(size_t)gr * 128 + c0 + j] : 0.f;
            y[j] = fmaxf((xv - mcol) * sc, 0.f);
        }
        if (gr >= n) {
            #pragma unroll
            for (int j = 0; j < 8; j++) y[j] = 0.f;
        }
        uint4 pk;
        __half2 h0 = __floats2half2_rn(y[0], y[1]);
        __half2 h1 = __floats2half2_rn(y[2], y[3]);
        __half2 h2 = __floats2half2_rn(y[4], y[5]);
        __half2 h3 = __floats2half2_rn(y[6], y[7]);
        pk.x = *(uint32_t*)&h0; pk.y = *(uint32_t*)&h1;
        pk.z = *(uint32_t*)&h2; pk.w = *(uint32_t*)&h3;
        *(uint4*)(smem + SM_A + (r * SMS + c0) * 2) = pk;
    }
    __syncthreads();

    uint32_t sb = smem_u32(smem);
    int wid = tid >> 5, lane = tid & 31;
    int rowbase = wid * 16;
    int a_row  = (lane & 7) + ((lane >> 3) & 1) * 8;
    int a_koff = (lane >> 4) * 8;
    int b_nrow = ((lane >> 4) * 8) + (lane & 7);
    int b_koff = ((lane >> 3) & 1) * 8;

    float acc[16][4];
    #pragma unroll
    for (int j = 0; j < 16; j++)
        #pragma unroll
        for (int q = 0; q < 4; q++) acc[j][q] = 0.f;

    for (int ks = 0; ks < 8; ks++) {
        uint32_t a0[4];
        uint32_t aaddr = sb + SM_A + (uint32_t)(((rowbase + a_row) * SMS + a_koff + ks * 16) * 2);
        ldmx4(a0, aaddr);
        #pragma unroll
        for (int p = 0; p < 8; p++) {
            uint32_t b[4];
            uint32_t baddr = sb + SM_B + (uint32_t)(((p * 16 + b_nrow) * SMS + b_koff + ks * 16) * 2);
            ldmx4(b, baddr);
            mma16816(acc[2 * p + 0], a0, b[0], b[1]);
            mma16816(acc[2 * p + 1], a0, b[2], b[3]);
        }
    }

    int g = lane >> 2, i4 = lane & 3;
    int r0 = m0 + rowbase + g;
    #pragma unroll
    for (int nt = 0; nt < 16; nt++) {
        int col = nt * 8 + i4 * 2;
        if (r0 < n)
            *(__half2*)(outh + (size_t)r0 * 128 + col) =
                __floats2half2_rn(acc[nt][0], acc[nt][1]);
        if (r0 + 8 < n)
            *(__half2*)(outh + (size_t)(r0 + 8) * 128 + col) =
                __floats2half2_rn(acc[nt][2], acc[nt][3]);
    }
}

// ---------------- aggregation: out[d] = b + sum_e w_e * h[src_e] (128 ch) ----
// modes: 0 = fp32 out + fused IN-stats accumulation; 1 = relu->fp16; 3 = tanh->fp16
__global__ __launch_bounds__(256) void k_agg128(
    const __half* __restrict__ h, const float* __restrict__ bias,
    float* __restrict__ outF, __half* __restrict__ outHalf,
    int n, int mode)
{
    __shared__ float ssum[128], ssq[128];
    int tid = threadIdx.x;
    if (mode == 0) {
        if (tid < 128) { ssum[tid] = 0.f; ssq[tid] = 0.f; }
        __syncthreads();
    }
    int node = blockIdx.x * 8 + (tid >> 5);
    int lane = tid & 31;
    bool valid = node < n;
    float4 acc = ((const float4*)bias)[lane];
    int e = 0, e1 = 0;
    if (valid) { e = g_rp[node]; e1 = g_rp[node + 1]; }
    for (; e + 8 <= e1; e += 8) {
        int s[8]; float w[8]; uint2 r[8];
        #pragma unroll
        for (int q = 0; q < 8; q++) { s[q] = g_csrc[e + q]; w[q] = g_cw[e + q]; }
        #pragma unroll
        for (int q = 0; q < 8; q++) r[q] = ((const uint2*)(h + (size_t)s[q] * 128))[lane];
        #pragma unroll
        for (int q = 0; q < 8; q++) acc_row(acc, r[q], w[q]);
    }
    for (; e + 4 <= e1; e += 4) {
        int s[4]; float w[4]; uint2 r[4];
        #pragma unroll
        for (int q = 0; q < 4; q++) { s[q] = g_csrc[e + q]; w[q] = g_cw[e + q]; }
        #pragma unroll
        for (int q = 0; q < 4; q++) r[q] = ((const uint2*)(h + (size_t)s[q] * 128))[lane];
        #pragma unroll
        for (int q = 0; q < 4; q++) acc_row(acc, r[q], w[q]);
    }
    for (; e < e1; ++e) {
        int s = g_csrc[e]; float w = g_cw[e];
        uint2 rv = ((const uint2*)(h + (size_t)s * 128))[lane];
        acc_row(acc, rv, w);
    }
    if (mode == 0) {
        if (valid) {
            ((float4*)(outF + (size_t)node * 128))[lane] = acc;
            int c0 = lane * 4;
            atomicAdd(&ssum[c0 + 0], acc.x); atomicAdd(&ssq[c0 + 0], acc.x * acc.x);
            atomicAdd(&ssum[c0 + 1], acc.y); atomicAdd(&ssq[c0 + 1], acc.y * acc.y);
            atomicAdd(&ssum[c0 + 2], acc.z); atomicAdd(&ssq[c0 + 2], acc.z * acc.z);
            atomicAdd(&ssum[c0 + 3], acc.w); atomicAdd(&ssq[c0 + 3], acc.w * acc.w);
        }
        __syncthreads();
        if (tid < 128) {
            atomicAdd(&g_stats[tid], ssum[tid]);
            atomicAdd(&g_stats[128 + tid], ssq[tid]);
        }
    } else if (valid) {
        if (mode == 1) {
            acc.x = fmaxf(acc.x, 0.f); acc.y = fmaxf(acc.y, 0.f);
            acc.z = fmaxf(acc.z, 0.f); acc.w = fmaxf(acc.w, 0.f);
        } else if (mode == 3) {
            acc.x = tanhf(acc.x); acc.y = tanhf(acc.y);
            acc.z = tanhf(acc.z); acc.w = tanhf(acc.w);
        }
        half_store4(acc, outHalf + (size_t)node * 128 + lane * 4);
    }
}

// ---------------- misc small kernels ------------------------------------------
__global__ void k_copyF0(const float* __restrict__ F0, int n) {
    int i = blockIdx.x * blockDim.x + threadIdx.x;
    if (i < n) ((float4*)g_F)[i] = ((const float4*)F0)[i];
}

// h = F @ W0[0:4] + M0 (fp16 out); block 0 zeroes g_stats for the next agg
__global__ __launch_bounds__(256) void k_conv0_diff(const float* __restrict__ W0, int n) {
    if (blockIdx.x == 0 && threadIdx.x < 256) g_stats[threadIdx.x] = 0.f;
    int node = blockIdx.x * 8 + (threadIdx.x >> 5);
    if (node >= n) return;
    int lane = threadIdx.x & 31;
    float4 Fv = ((const float4*)g_F)[node];
    float4 m = ((const float4*)(g_M0 + (size_t)node * 128))[lane];
    const float4* w = (const float4*)W0;
    float4 w0 = w[0 * 32 + lane], w1 = w[1 * 32 + lane];
    float4 w2 = w[2 * 32 + lane], w3 = w[3 * 32 + lane];
    m.x += Fv.x * w0.x + Fv.y * w1.x + Fv.z * w2.x + Fv.w * w3.x;
    m.y += Fv.x * w0.y + Fv.y * w1.y + Fv.z * w2.y + Fv.w * w3.y;
    m.z += Fv.x * w0.z + Fv.y * w1.z + Fv.z * w2.z + Fv.w * w3.z;
    m.w += Fv.x * w0.w + Fv.y * w1.w + Fv.z * w2.w + Fv.w * w3.w;
    half_store4(m, g_h + (size_t)node * 128 + lane * 4);
}

// out[n][4] = x[n][128] @ W[128][4]
__global__ __launch_bounds__(256) void k_gemm_h4(
    const float* __restrict__ x, const float* __restrict__ W,
    float* __restrict__ out, int n)
{
    int warp = blockIdx.x * 8 + (threadIdx.x >> 5);
    if (warp >= n) return;
    int lane = threadIdx.x & 31;
    float4 xv = ((const float4*)(x + (size_t)warp * HID))[lane];
    const float4* Wv = (const float4*)W;
    float4 w0 = Wv[lane * 4 + 0], w1 = Wv[lane * 4 + 1];
    float4 w2 = Wv[lane * 4 + 2], w3 = Wv[lane * 4 + 3];
    float4 p;
    p.x = xv.x * w0.x + xv.y * w1.x + xv.z * w2.x + xv.w * w3.x;
    p.y = xv.x * w0.y + xv.y * w1.y + xv.z * w2.y + xv.w * w3.y;
    p.z = xv.x * w0.z + xv.y * w1.z + xv.z * w2.z + xv.w * w3.z;
    p.w = xv.x * w0.w + xv.y * w1.w + xv.z * w2.w + xv.w * w3.w;
    #pragma unroll
    for (int o = 16; o > 0; o >>= 1) {
        p.x += __shfl_xor_sync(0xFFFFFFFFu, p.x, o);
        p.y += __shfl_xor_sync(0xFFFFFFFFu, p.y, o);
        p.z += __shfl_xor_sync(0xFFFFFFFFu, p.z, o);
        p.w += __shfl_xor_sync(0xFFFFFFFFu, p.w, o);
    }
    if (lane == 0) ((float4*)out)[warp] = p;
}

// fused: 4-channel aggregation + bias + tanh -> F_dot; F update; write outputs
__global__ void k_agg4_step(const float* __restrict__ h4, const float* __restrict__ b,
                            float* __restrict__ out, int n, int T, int t)
{
    int i = blockIdx.x * blockDim.x + threadIdx.x;
    if (i >= n) return;
    float4 acc = *(const float4*)b;
    int e0 = g_rp[i], e1 = g_rp[i + 1];
    for (int e = e0; e < e1; ++e) {
        int s = g_csrc[e]; float w = g_cw[e];
        float4 hv = ((const float4*)h4)[s];
        acc.x += w * hv.x; acc.y += w * hv.y; acc.z += w * hv.z; acc.w += w * hv.w;
    }
    float4 fd;
    fd.x = tanhf(acc.x); fd.y = tanhf(acc.y);
    fd.z = tanhf(acc.z); fd.w = tanhf(acc.w);
    float4 fc = ((const float4*)g_F)[i];
    float4 fn;
    fn.x = tanhf(fc.x + fd.x * DTV);
    fn.y = tanhf(fc.y + fd.y * DTV);
    fn.z = tanhf(fc.z + fd.z * DTV);
    fn.w = tanhf(fc.w + fd.w * DTV);
    ((float4*)g_F)[i] = fn;
    float4* ob = (float4*)out;
    ob[(size_t)i * T + t] = fn;                     // Fs     [N][T][4]
    ob[(size_t)n * T + (size_t)i * T + t] = fd;     // F_dots [N][T][4]
}

// ---------------- host orchestration ------------------------------------------
extern "C" void kernel_launch(void* const* d_in, const int* in_sizes, int n_in,
                              void* d_out, int out_size)
{
    const float* F0    = (const float*)d_in[0];
    const int*   ei    = (const int*)d_in[1];
    const float* meshf = (const float*)d_in[2];
    const float* mW0   = (const float*)d_in[4];
    const float* mb0   = (const float*)d_in[5];
    const float* mWh   = (const float*)d_in[6];
    const float* mbh   = (const float*)d_in[7];
    const float* mW9   = (const float*)d_in[8];
    const float* mb9   = (const float*)d_in[9];
    const float* dW0   = (const float*)d_in[10];
    const float* db0   = (const float*)d_in[11];
    const float* dWh   = (const float*)d_in[12];
    const float* dbh   = (const float*)d_in[13];
    const float* dW9   = (const float*)d_in[14];
    const float* db9   = (const float*)d_in[15];
    float* out = (float*)d_out;

    int N = in_sizes[0] / 4;
    int E = in_sizes[1] / 2;
    int T = out_size / (2 * N * 4);
    if (N > MAXN || E > MAXE || T <= 0) return;

    float *bufA, *M0buf, *h4;
    __half *hbuf, *Abuf, *Bbuf;
    cudaGetSymbolAddress((void**)&hbuf,  g_h);
    cudaGetSymbolAddress((void**)&bufA,  g_bufA);
    cudaGetSymbolAddress((void**)&M0buf, g_M0);
    cudaGetSymbolAddress((void**)&h4,    g_h4);
    cudaGetSymbolAddress((void**)&Abuf,  g_A);
    cudaGetSymbolAddress((void**)&Bbuf,  g_B);

    cudaFuncSetAttribute(k_mmagemm,    cudaFuncAttributeMaxDynamicSharedMemorySize, GEMM_SMEM);
    cudaFuncSetAttribute(k_mmagemm_in, cudaFuncAttributeMaxDynamicSharedMemorySize, GEMM_SMEM);

    int gN = (N + 255) / 256;
    int gE = (E + 255) / 256;
    int gMM = (N + 127) / 128;   // GEMM M-tiles of 128
    int gA = (N + 7) / 8;
    int nb = (N + 255) / 256;
    float inv_n = 1.f / (float)N;

    // ---- graph preprocessing ----
    k_init_deg<<<gN, 256>>>(N);
    k_count<<<gE, 256>>>(ei, E);
    k_dinv<<<gN, 256>>>(N);
    k_scan1<<<nb, 256>>>(N);
    k_scan2<<<1, 256>>>(nb, N);
    k_scan3<<<gN, 256>>>(N);
    k_fill<<<(E + N + 255) / 256, 256>>>(ei, E, N);

    // ---- weight conversion (all 19 slots in one launch) ----
    WTab wt;
    wt.src[0] = mW0;  wt.K[0] = 8;   wt.Kp[0] = 16;            // mesh conv0
    for (int l = 0; l < 8; ++l) { wt.src[1 + l] = mWh + (size_t)l * HID * HID; wt.K[1 + l] = 128; wt.Kp[1 + l] = 128; }
    wt.src[9] = mW9;  wt.K[9] = 128; wt.Kp[9] = 128;           // mesh conv9
    for (int l = 0; l < 8; ++l) { wt.src[10 + l] = dWh + (size_t)l * HID * HID; wt.K[10 + l] = 128; wt.Kp[10 + l] = 128; }
    wt.src[18] = dW0 + 4 * HID; wt.K[18] = 128; wt.Kp[18] = 128;  // diff W0 mesh rows 4..131
    k_wconv<<<dim3(64, NSLOT), 256>>>(wt);

    // ---- mesh descriptor block ----
    k_meshin<<<(N * 16 + 255) / 256, 256>>>(meshf, N);            // + zero stats
    k_mmagemm<<<gMM, 256, GEMM_SMEM>>>(Abuf, Bbuf, hbuf, N, 16, 1);
    k_agg128<<<gA, 256>>>(hbuf, mb0, bufA, Abuf, N, 0);           // fp32 + fused stats
    k_mmagemm_in<<<gMM, 256, GEMM_SMEM>>>(bufA,                   // IN+relu+GEMM W_h0
        Bbuf + (size_t)1 * SLOT_ELEMS, hbuf, N, inv_n);
    for (int l = 1; l < 8; ++l) {
        k_agg128<<<gA, 256>>>(hbuf, mbh + (size_t)(l - 1) * HID, bufA, Abuf, N, 1);
        k_mmagemm<<<gMM, 256, GEMM_SMEM>>>(Abuf,
            Bbuf + (size_t)(1 + l) * SLOT_ELEMS, hbuf, N, 128, 1);
    }
    k_agg128<<<gA, 256>>>(hbuf, mbh + (size_t)7 * HID, bufA, Abuf, N, 1);
    k_mmagemm<<<gMM, 256, GEMM_SMEM>>>(Abuf,
        Bbuf + (size_t)9 * SLOT_ELEMS, hbuf, N, 128, 1);          // conv9
    k_agg128<<<gA, 256>>>(hbuf, mb9, bufA, Abuf, N, 3);           // tanh -> mesh fp16

    // ---- precompute M0 = mesh @ dW0[4:132]  (time-invariant, fp32) ----
    k_mmagemm<<<gMM, 256, GEMM_SMEM>>>(Abuf,
        Bbuf + (size_t)18 * SLOT_ELEMS, M0buf, N, 128, 0);

    // ---- time stepping ----
    k_copyF0<<<gN, 256>>>(F0, N);
    for (int t = 0; t < T; ++t) {
        k_conv0_diff<<<gA, 256>>>(dW0, N);                        // + zero stats
        k_agg128<<<gA, 256>>>(hbuf, db0, bufA, Abuf, N, 0);       // fp32 + fused stats
        k_mmagemm_in<<<gMM, 256, GEMM_SMEM>>>(bufA,               // IN+relu+GEMM W_h0
            Bbuf + (size_t)10 * SLOT_ELEMS, hbuf, N, inv_n);
        for (int l = 1; l < 8; ++l) {
            k_agg128<<<gA, 256>>>(hbuf, dbh + (size_t)(l - 1) * HID, bufA, Abuf, N, 1);
            k_mmagemm<<<gMM, 256, GEMM_SMEM>>>(Abuf,
                Bbuf + (size_t)(10 + l) * SLOT_ELEMS, hbuf, N, 128, 1);
        }
        k_agg128<<<gA, 256>>>(hbuf, dbh + (size_t)7 * HID, bufA, Abuf, N, 2 - 2);  // mode 0? no: plain fp32
        k_gemm_h4<<<gA, 256>>>(bufA, dW9, h4, N);
        k_agg4_step<<<gN, 256>>>(h4, db9, out, N, T, t);
    }
}

// round 14
// speedup vs baseline: 1.3327x; 1.1679x over previous
#include <cuda_runtime.h>
#include <cuda_fp16.h>
#include <math.h>
#include <stdint.h>

// Problem constants (fixed for this dataset)
#define MAXN 30000
#define MAXE 480000
#define MAXNE (MAXE + MAXN)
#define HID 128
#define EPSV 1e-5f
#define DTV 0.1f
#define NSLOT 19
#define SLOT_ELEMS (128 * 128)

// ---------------- scratch (static device memory; no runtime allocs) ----------
__device__ int   g_deg[MAXN];
__device__ float g_dinv[MAXN];
__device__ int   g_rp[MAXN + 1];
__device__ int   g_cur[MAXN];
__device__ int   g_csrc[MAXNE];
__device__ float g_cw[MAXNE];
__device__ float g_stats[2 * HID];
__device__ int   g_lex[MAXN];
__device__ int   g_bsum[256];

__device__ __align__(16) __half g_h[(size_t)MAXN * HID];    // GEMM output (pre-aggregation), fp16
__device__ __align__(16) float g_bufA[(size_t)MAXN * HID];  // fp32 activations (IN input)
__device__ __align__(16) float g_M0[(size_t)MAXN * HID];    // precomputed mesh @ W0[4:132]
__device__ __align__(16) float g_F[MAXN * 4];
__device__ __align__(16) float g_h4[MAXN * 4];

// fp16 GEMM operand buffers
__device__ __align__(16) __half g_A[(size_t)MAXN * HID];
__device__ __align__(16) __half g_B[NSLOT * SLOT_ELEMS];

// ---------------- helpers -----------------------------------------------------
__device__ __forceinline__ uint32_t smem_u32(const void* p) {
    uint32_t a;
    asm("{ .reg .u64 t; cvta.to.shared.u64 t, %1; cvt.u32.u64 %0, t; }" : "=r"(a) : "l"(p));
    return a;
}

__device__ __forceinline__ void ldmx4(uint32_t* r, uint32_t addr) {
    asm volatile("ldmatrix.sync.aligned.m8n8.x4.shared.b16 {%0,%1,%2,%3}, [%4];"
                 : "=r"(r[0]), "=r"(r[1]), "=r"(r[2]), "=r"(r[3]) : "r"(addr));
}

__device__ __forceinline__ void mma16816(float* c, const uint32_t* a, uint32_t b0, uint32_t b1) {
    asm volatile("mma.sync.aligned.m16n8k16.row.col.f32.f16.f16.f32 "
                 "{%0,%1,%2,%3}, {%4,%5,%6,%7}, {%8,%9}, {%0,%1,%2,%3};"
                 : "+f"(c[0]), "+f"(c[1]), "+f"(c[2]), "+f"(c[3])
                 : "r"(a[0]), "r"(a[1]), "r"(a[2]), "r"(a[3]), "r"(b0), "r"(b1));
}

__device__ __forceinline__ void half_store4(float4 v, __half* p) {
    __half2 h01 = __floats2half2_rn(v.x, v.y);
    __half2 h23 = __floats2half2_rn(v.z, v.w);
    uint2 pk;
    pk.x = *(uint32_t*)&h01; pk.y = *(uint32_t*)&h23;
    *(uint2*)p = pk;
}

__device__ __forceinline__ void acc_row(float4& acc, uint2 raw, float w) {
    float2 f01 = __half22float2(*(__half2*)&raw.x);
    float2 f23 = __half22float2(*(__half2*)&raw.y);
    acc.x += w * f01.x; acc.y += w * f01.y;
    acc.z += w * f23.x; acc.w += w * f23.y;
}

// ---------------- graph preprocessing ----------------------------------------
__global__ void k_init_deg(int n) {
    int i = blockIdx.x * blockDim.x + threadIdx.x;
    if (i < n) g_deg[i] = 1;  // self-loop
}

__global__ void k_count(const int* __restrict__ ei, int E) {
    int e = blockIdx.x * blockDim.x + threadIdx.x;
    if (e < E) atomicAdd(&g_deg[ei[E + e]], 1);
}

__global__ void k_dinv(int n) {
    int i = blockIdx.x * blockDim.x + threadIdx.x;
    if (i < n) g_dinv[i] = rsqrtf((float)g_deg[i]);
}

// multi-block exclusive scan: scan1 (local) -> scan2 (block sums) -> scan3 (add)
__global__ void k_scan1(int n) {
    __shared__ int ws[8];
    int b = blockIdx.x, t = threadIdx.x;
    int i = b * 256 + t;
    int lane = t & 31, w = t >> 5;
    int v = (i < n) ? g_deg[i] : 0;
    int x = v;
    #pragma unroll
    for (int o = 1; o < 32; o <<= 1) {
        int t2 = __shfl_up_sync(0xFFFFFFFFu, x, o);
        if (lane >= o) x += t2;
    }
    if (lane == 31) ws[w] = x;
    __syncthreads();
    if (w == 0) {
        int s = (lane < 8) ? ws[lane] : 0;
        #pragma unroll
        for (int o = 1; o < 8; o <<= 1) {
            int t2 = __shfl_up_sync(0xFFFFFFFFu, s, o);
            if (lane >= o) s += t2;
        }
        if (lane < 8) ws[lane] = s;
    }
    __syncthreads();
    int woff = (w > 0) ? ws[w - 1] : 0;
    if (i < n) g_lex[i] = woff + x - v;
    if (t == 255) g_bsum[b] = woff + x;
}

__global__ void k_scan2(int nb, int n) {
    __shared__ int ws[8];
    int t = threadIdx.x;
    int lane = t & 31, w = t >> 5;
    int v = (t < nb) ? g_bsum[t] : 0;
    int x = v;
    #pragma unroll
    for (int o = 1; o < 32; o <<= 1) {
        int t2 = __shfl_up_sync(0xFFFFFFFFu, x, o);
        if (lane >= o) x += t2;
    }
    if (lane == 31) ws[w] = x;
    __syncthreads();
    if (w == 0) {
        int s = (lane < 8) ? ws[lane] : 0;
        #pragma unroll
        for (int o = 1; o < 8; o <<= 1) {
            int t2 = __shfl_up_sync(0xFFFFFFFFu, s, o);
            if (lane >= o) s += t2;
        }
        if (lane < 8) ws[lane] = s;
    }
    __syncthreads();
    int woff = (w > 0) ? ws[w - 1] : 0;
    int excl = woff + x - v;
    __syncthreads();
    if (t < nb) g_bsum[t] = excl;
    if (t == nb - 1) g_rp[n] = woff + x;
}

__global__ void k_scan3(int n) {
    int i = blockIdx.x * blockDim.x + threadIdx.x;
    if (i < n) {
        int v = g_lex[i] + g_bsum[i >> 8];
        g_rp[i] = v;
        g_cur[i] = v;
    }
}

__global__ void k_fill(const int* __restrict__ ei, int E, int n) {
    int idx = blockIdx.x * blockDim.x + threadIdx.x;
    if (idx < E) {
        int s = ei[idx], d = ei[E + idx];
        int pos = atomicAdd(&g_cur[d], 1);
        g_csrc[pos] = s;
        g_cw[pos] = g_dinv[s] * g_dinv[d];
    } else if (idx < E + n) {
        int i = idx - E;
        int pos = atomicAdd(&g_cur[i], 1);
        g_csrc[pos] = i;
        g_cw[pos] = g_dinv[i] * g_dinv[i];
    }
}

// ---------------- weight conversion: W[KxN] fp32 -> B[NxKpad] fp16 -----------
struct WTab {
    const float* src[NSLOT];
    int K[NSLOT];
    int Kp[NSLOT];
};

__global__ void k_wconv(WTab t) {
    int slot = blockIdx.y;
    int Kp = t.Kp[slot];
    int idx = blockIdx.x * 256 + threadIdx.x;
    if (idx >= 128 * Kp) return;
    int nrow = idx / Kp, k = idx % Kp;
    float v = (k < t.K[slot]) ? t.src[slot][(size_t)k * 128 + nrow] : 0.0f;
    g_B[slot * SLOT_ELEMS + idx] = __float2half(v);
}

// meshfield [Nx8] fp32 -> fp16 [Nx16] (cols 8..15 zero)
__global__ void k_meshin(const float* __restrict__ mf, int n) {
    int idx = blockIdx.x * blockDim.x + threadIdx.x;
    if (idx >= n * 16) return;
    int node = idx >> 4, c = idx & 15;
    float v = (c < 8) ? mf[node * 8 + c] : 0.0f;
    g_A[idx] = __float2half(v);
}

// ---------------- mma.sync fp16 GEMM, M-tile 128 ------------------------------
#define SMS 136                         // smem row stride in halves (128 + 8 pad)
#define SM_A 0
#define SM_B (128 * SMS * 2)            // 34816
#define GEMM_SMEM (SM_B + 128 * SMS * 2)  // 69632 bytes

__global__ __launch_bounds__(256) void k_mmagemm(
    const __half* __restrict__ A, const __half* __restrict__ B,
    void* __restrict__ outp, int n, int K, int out_half)
{
    extern __shared__ __align__(16) char smem[];
    int tid = threadIdx.x;
    int m0 = blockIdx.x * 128;
    int nb8 = K >> 3;

    for (int idx = tid; idx < 128 * nb8; idx += 256) {
        int r = idx / nb8, c = idx - r * nb8;
        uint4 v = *(const uint4*)(B + (size_t)r * K + c * 8);
        *(uint4*)(smem + SM_B + (r * SMS + c * 8) * 2) = v;
    }
    for (int idx = tid; idx < 128 * nb8; idx += 256) {
        int r = idx / nb8, c = idx - r * nb8;
        int gr = m0 + r;
        uint4 v = make_uint4(0, 0, 0, 0);
        if (gr < n) v = *(const uint4*)(A + (size_t)gr * K + c * 8);
        *(uint4*)(smem + SM_A + (r * SMS + c * 8) * 2) = v;
    }
    __syncthreads();

    uint32_t sb = smem_u32(smem);
    int wid = tid >> 5, lane = tid & 31;
    int rowbase = wid * 16;

    int a_row  = (lane & 7) + ((lane >> 3) & 1) * 8;
    int a_koff = (lane >> 4) * 8;
    int b_nrow = ((lane >> 4) * 8) + (lane & 7);
    int b_koff = ((lane >> 3) & 1) * 8;

    float acc[16][4];
    #pragma unroll
    for (int j = 0; j < 16; j++)
        #pragma unroll
        for (int q = 0; q < 4; q++) acc[j][q] = 0.f;

    int ksteps = K >> 4;
    for (int ks = 0; ks < ksteps; ks++) {
        uint32_t a0[4];
        uint32_t aaddr = sb + SM_A + (uint32_t)(((rowbase + a_row) * SMS + a_koff + ks * 16) * 2);
        ldmx4(a0, aaddr);
        #pragma unroll
        for (int p = 0; p < 8; p++) {
            uint32_t b[4];
            uint32_t baddr = sb + SM_B + (uint32_t)(((p * 16 + b_nrow) * SMS + b_koff + ks * 16) * 2);
            ldmx4(b, baddr);
            mma16816(acc[2 * p + 0], a0, b[0], b[1]);
            mma16816(acc[2 * p + 1], a0, b[2], b[3]);
        }
    }

    int g = lane >> 2, i4 = lane & 3;
    int r0 = m0 + rowbase + g;
    if (out_half) {
        __half* out = (__half*)outp;
        #pragma unroll
        for (int nt = 0; nt < 16; nt++) {
            int col = nt * 8 + i4 * 2;
            if (r0 < n)
                *(__half2*)(out + (size_t)r0 * 128 + col) =
                    __floats2half2_rn(acc[nt][0], acc[nt][1]);
            if (r0 + 8 < n)
                *(__half2*)(out + (size_t)(r0 + 8) * 128 + col) =
                    __floats2half2_rn(acc[nt][2], acc[nt][3]);
        }
    } else {
        float* out = (float*)outp;
        #pragma unroll
        for (int nt = 0; nt < 16; nt++) {
            int col = nt * 8 + i4 * 2;
            if (r0 < n)
                *(float2*)(out + (size_t)r0 * 128 + col) = make_float2(acc[nt][0], acc[nt][1]);
            if (r0 + 8 < n)
                *(float2*)(out + (size_t)(r0 + 8) * 128 + col) = make_float2(acc[nt][2], acc[nt][3]);
        }
    }
}

// ---------------- aggregation: out[d] = b + sum_e w_e * h[src_e] (128 ch) ----
// h is fp16 (256B rows). mode 0: fp32 out (+zero stats); 1: relu->fp16; 3: tanh->fp16
__global__ __launch_bounds__(256) void k_agg128(
    const __half* __restrict__ h, const float* __restrict__ bias,
    float* __restrict__ outF, __half* __restrict__ outHalf,
    int n, int mode)
{
    if (mode == 0 && blockIdx.x == 0) g_stats[threadIdx.x] = 0.f;  // fold zero_stats
    int node = blockIdx.x * 8 + (threadIdx.x >> 5);
    if (node >= n) return;
    int lane = threadIdx.x & 31;
    float4 acc = ((const float4*)bias)[lane];
    int e = g_rp[node], e1 = g_rp[node + 1];
    for (; e + 8 <= e1; e += 8) {
        int s[8]; float w[8]; uint2 r[8];
        #pragma unroll
        for (int q = 0; q < 8; q++) { s[q] = g_csrc[e + q]; w[q] = g_cw[e + q]; }
        #pragma unroll
        for (int q = 0; q < 8; q++) r[q] = ((const uint2*)(h + (size_t)s[q] * 128))[lane];
        #pragma unroll
        for (int q = 0; q < 8; q++) acc_row(acc, r[q], w[q]);
    }
    for (; e + 4 <= e1; e += 4) {
        int s[4]; float w[4]; uint2 r[4];
        #pragma unroll
        for (int q = 0; q < 4; q++) { s[q] = g_csrc[e + q]; w[q] = g_cw[e + q]; }
        #pragma unroll
        for (int q = 0; q < 4; q++) r[q] = ((const uint2*)(h + (size_t)s[q] * 128))[lane];
        #pragma unroll
        for (int q = 0; q < 4; q++) acc_row(acc, r[q], w[q]);
    }
    for (; e < e1; ++e) {
        int s = g_csrc[e]; float w = g_cw[e];
        uint2 rv = ((const uint2*)(h + (size_t)s * 128))[lane];
        acc_row(acc, rv, w);
    }
    if (mode == 0) {
        ((float4*)(outF + (size_t)node * 128))[lane] = acc;
    } else {
        if (mode == 1) {
            acc.x = fmaxf(acc.x, 0.f); acc.y = fmaxf(acc.y, 0.f);
            acc.z = fmaxf(acc.z, 0.f); acc.w = fmaxf(acc.w, 0.f);
        } else if (mode == 3) {
            acc.x = tanhf(acc.x); acc.y = tanhf(acc.y);
            acc.z = tanhf(acc.z); acc.w = tanhf(acc.w);
        }
        half_store4(acc, outHalf + (size_t)node * 128 + lane * 4);
    }
}

// ---------------- FUSED final conv9: h4 = (agg(h)+b) @ W9  --------------------
// Same gather as k_agg128, then the k_gemm_h4 dot (identical order) in-register.
__global__ __launch_bounds__(256) void k_agg_h4(
    const __half* __restrict__ h, const float* __restrict__ bias,
    const float* __restrict__ W9, float* __restrict__ h4, int n)
{
    int node = blockIdx.x * 8 + (threadIdx.x >> 5);
    if (node >= n) return;
    int lane = threadIdx.x & 31;
    float4 acc = ((const float4*)bias)[lane];
    int e = g_rp[node], e1 = g_rp[node + 1];
    for (; e + 8 <= e1; e += 8) {
        int s[8]; float w[8]; uint2 r[8];
        #pragma unroll
        for (int q = 0; q < 8; q++) { s[q] = g_csrc[e + q]; w[q] = g_cw[e + q]; }
        #pragma unroll
        for (int q = 0; q < 8; q++) r[q] = ((const uint2*)(h + (size_t)s[q] * 128))[lane];
        #pragma unroll
        for (int q = 0; q < 8; q++) acc_row(acc, r[q], w[q]);
    }
    for (; e + 4 <= e1; e += 4) {
        int s[4]; float w[4]; uint2 r[4];
        #pragma unroll
        for (int q = 0; q < 4; q++) { s[q] = g_csrc[e + q]; w[q] = g_cw[e + q]; }
        #pragma unroll
        for (int q = 0; q < 4; q++) r[q] = ((const uint2*)(h + (size_t)s[q] * 128))[lane];
        #pragma unroll
        for (int q = 0; q < 4; q++) acc_row(acc, r[q], w[q]);
    }
    for (; e < e1; ++e) {
        int s = g_csrc[e]; float w = g_cw[e];
        uint2 rv = ((const uint2*)(h + (size_t)s * 128))[lane];
        acc_row(acc, rv, w);
    }
    // dot with W9 (layout/order identical to the old k_gemm_h4)
    const float4* Wv = (const float4*)W9;
    float4 w0 = Wv[lane * 4 + 0], w1 = Wv[lane * 4 + 1];
    float4 w2 = Wv[lane * 4 + 2], w3 = Wv[lane * 4 + 3];
    float4 p;
    p.x = acc.x * w0.x + acc.y * w1.x + acc.z * w2.x + acc.w * w3.x;
    p.y = acc.x * w0.y + acc.y * w1.y + acc.z * w2.y + acc.w * w3.y;
    p.z = acc.x * w0.z + acc.y * w1.z + acc.z * w2.z + acc.w * w3.z;
    p.w = acc.x * w0.w + acc.y * w1.w + acc.z * w2.w + acc.w * w3.w;
    #pragma unroll
    for (int o = 16; o > 0; o >>= 1) {
        p.x += __shfl_xor_sync(0xFFFFFFFFu, p.x, o);
        p.y += __shfl_xor_sync(0xFFFFFFFFu, p.y, o);
        p.z += __shfl_xor_sync(0xFFFFFFFFu, p.z, o);
        p.w += __shfl_xor_sync(0xFFFFFFFFu, p.w, o);
    }
    if (lane == 0) ((float4*)h4)[node] = p;
}

// ---------------- instance norm ----------------------------------------------
__global__ __launch_bounds__(128) void k_in_stats(const float* __restrict__ x, int n) {
    int c = threadIdx.x;
    int chunk = (n + gridDim.x - 1) / gridDim.x;
    int r0 = blockIdx.x * chunk;
    int r1 = min(n, r0 + chunk);
    float s = 0.f, q = 0.f;
    for (int r = r0; r < r1; ++r) {
        float v = x[(size_t)r * HID + c];
        s += v; q += v * v;
    }
    atomicAdd(&g_stats[c], s);
    atomicAdd(&g_stats[HID + c], q);
}

// apply IN, then ReLU, write fp16 (feeds first middle conv)
__global__ void k_in_apply_half(const float* __restrict__ x, int n) {
    int idx = blockIdx.x * blockDim.x + threadIdx.x;
    if (idx >= n * HID) return;
    int c = idx & (HID - 1);
    float inv_n = 1.f / (float)n;
    float m = g_stats[c] * inv_n;
    float v = g_stats[HID + c] * inv_n - m * m;
    float y = (x[idx] - m) * rsqrtf(v + EPSV);
    y = fmaxf(y, 0.f);
    g_A[idx] = __float2half(y);
}

// ---------------- misc small kernels ------------------------------------------
__global__ void k_copyF0(const float* __restrict__ F0, int n) {
    int i = blockIdx.x * blockDim.x + threadIdx.x;
    if (i < n) ((float4*)g_F)[i] = ((const float4*)F0)[i];
}

// h = F @ W0[0:4] + M0   (diff conv0, mesh part precomputed), fp16 out
// Used ONCE before the time loop; later steps produce h inside k_step_fused.
__global__ __launch_bounds__(256) void k_conv0_diff(const float* __restrict__ W0, int n) {
    int node = blockIdx.x * 8 + (threadIdx.x >> 5);
    if (node >= n) return;
    int lane = threadIdx.x & 31;
    float4 Fv = ((const float4*)g_F)[node];
    float4 m = ((const float4*)(g_M0 + (size_t)node * 128))[lane];
    const float4* w = (const float4*)W0;
    float4 w0 = w[0 * 32 + lane], w1 = w[1 * 32 + lane];
    float4 w2 = w[2 * 32 + lane], w3 = w[3 * 32 + lane];
    m.x += Fv.x * w0.x + Fv.y * w1.x + Fv.z * w2.x + Fv.w * w3.x;
    m.y += Fv.x * w0.y + Fv.y * w1.y + Fv.z * w2.y + Fv.w * w3.y;
    m.z += Fv.x * w0.z + Fv.y * w1.z + Fv.z * w2.z + Fv.w * w3.z;
    m.w += Fv.x * w0.w + Fv.y * w1.w + Fv.z * w2.w + Fv.w * w3.w;
    half_store4(m, g_h + (size_t)node * 128 + lane * 4);
}

// ---------------- FUSED step: agg4(h4)+tanh -> F_dot; F update; outputs;
//                  AND next-step conv0 h = F_new @ W0[0:4] + M0 -----------------
// Warp per node; edge gather is redundant across lanes (broadcast loads).
__global__ __launch_bounds__(256) void k_step_fused(
    const float* __restrict__ h4, const float* __restrict__ b,
    const float* __restrict__ W0, float* __restrict__ out,
    int n, int T, int t)
{
    int node = blockIdx.x * 8 + (threadIdx.x >> 5);
    if (node >= n) return;
    int lane = threadIdx.x & 31;
    float4 acc = *(const float4*)b;
    int e0 = g_rp[node], e1 = g_rp[node + 1];
    for (int e = e0; e < e1; ++e) {
        int s = g_csrc[e]; float w = g_cw[e];
        float4 hv = ((const float4*)h4)[s];
        acc.x += w * hv.x; acc.y += w * hv.y; acc.z += w * hv.z; acc.w += w * hv.w;
    }
    float4 fd;
    fd.x = tanhf(acc.x); fd.y = tanhf(acc.y);
    fd.z = tanhf(acc.z); fd.w = tanhf(acc.w);
    float4 fc = ((const float4*)g_F)[node];
    float4 fn;
    fn.x = tanhf(fc.x + fd.x * DTV);
    fn.y = tanhf(fc.y + fd.y * DTV);
    fn.z = tanhf(fc.z + fd.z * DTV);
    fn.w = tanhf(fc.w + fd.w * DTV);
    if (lane == 0) {
        ((float4*)g_F)[node] = fn;
        float4* ob = (float4*)out;
        ob[(size_t)node * T + t] = fn;                       // Fs     [N][T][4]
        ob[(size_t)n * T + (size_t)node * T + t] = fd;       // F_dots [N][T][4]
    }
    // conv0 for the next step (harmless on the last step)
    float4 m = ((const float4*)(g_M0 + (size_t)node * 128))[lane];
    const float4* w = (const float4*)W0;
    float4 w0 = w[0 * 32 + lane], w1 = w[1 * 32 + lane];
    float4 w2 = w[2 * 32 + lane], w3 = w[3 * 32 + lane];
    m.x += fn.x * w0.x + fn.y * w1.x + fn.z * w2.x + fn.w * w3.x;
    m.y += fn.x * w0.y + fn.y * w1.y + fn.z * w2.y + fn.w * w3.y;
    m.z += fn.x * w0.z + fn.y * w1.z + fn.z * w2.z + fn.w * w3.z;
    m.w += fn.x * w0.w + fn.y * w1.w + fn.z * w2.w + fn.w * w3.w;
    half_store4(m, g_h + (size_t)node * 128 + lane * 4);
}

// ---------------- host orchestration ------------------------------------------
extern "C" void kernel_launch(void* const* d_in, const int* in_sizes, int n_in,
                              void* d_out, int out_size)
{
    const float* F0    = (const float*)d_in[0];
    const int*   ei    = (const int*)d_in[1];
    const float* meshf = (const float*)d_in[2];
    const float* mW0   = (const float*)d_in[4];
    const float* mb0   = (const float*)d_in[5];
    const float* mWh   = (const float*)d_in[6];
    const float* mbh   = (const float*)d_in[7];
    const float* mW9   = (const float*)d_in[8];
    const float* mb9   = (const float*)d_in[9];
    const float* dW0   = (const float*)d_in[10];
    const float* db0   = (const float*)d_in[11];
    const float* dWh   = (const float*)d_in[12];
    const float* dbh   = (const float*)d_in[13];
    const float* dW9   = (const float*)d_in[14];
    const float* db9   = (const float*)d_in[15];
    float* out = (float*)d_out;

    int N = in_sizes[0] / 4;
    int E = in_sizes[1] / 2;
    int T = out_size / (2 * N * 4);
    if (N > MAXN || E > MAXE || T <= 0) return;

    float *bufA, *M0buf, *h4;
    __half *hbuf, *Abuf, *Bbuf;
    cudaGetSymbolAddress((void**)&hbuf,  g_h);
    cudaGetSymbolAddress((void**)&bufA,  g_bufA);
    cudaGetSymbolAddress((void**)&M0buf, g_M0);
    cudaGetSymbolAddress((void**)&h4,    g_h4);
    cudaGetSymbolAddress((void**)&Abuf,  g_A);
    cudaGetSymbolAddress((void**)&Bbuf,  g_B);

    cudaFuncSetAttribute(k_mmagemm, cudaFuncAttributeMaxDynamicSharedMemorySize, GEMM_SMEM);

    int gN = (N + 255) / 256;
    int gE = (E + 255) / 256;
    int gMM = (N + 127) / 128;   // GEMM M-tiles of 128
    int gA = (N + 7) / 8;
    int nb = (N + 255) / 256;

    // ---- graph preprocessing ----
    k_init_deg<<<gN, 256>>>(N);
    k_count<<<gE, 256>>>(ei, E);
    k_dinv<<<gN, 256>>>(N);
    k_scan1<<<nb, 256>>>(N);
    k_scan2<<<1, 256>>>(nb, N);
    k_scan3<<<gN, 256>>>(N);
    k_fill<<<(E + N + 255) / 256, 256>>>(ei, E, N);

    // ---- weight conversion (all 19 slots in one launch) ----
    WTab wt;
    wt.src[0] = mW0;  wt.K[0] = 8;   wt.Kp[0] = 16;            // mesh conv0
    for (int l = 0; l < 8; ++l) { wt.src[1 + l] = mWh + (size_t)l * HID * HID; wt.K[1 + l] = 128; wt.Kp[1 + l] = 128; }
    wt.src[9] = mW9;  wt.K[9] = 128; wt.Kp[9] = 128;           // mesh conv9
    for (int l = 0; l < 8; ++l) { wt.src[10 + l] = dWh + (size_t)l * HID * HID; wt.K[10 + l] = 128; wt.Kp[10 + l] = 128; }
    wt.src[18] = dW0 + 4 * HID; wt.K[18] = 128; wt.Kp[18] = 128;  // diff W0 mesh rows 4..131
    k_wconv<<<dim3(64, NSLOT), 256>>>(wt);

    // ---- mesh descriptor block ----
    k_meshin<<<(N * 16 + 255) / 256, 256>>>(meshf, N);
    k_mmagemm<<<gMM, 256, GEMM_SMEM>>>(Abuf, Bbuf, hbuf, N, 16, 1);
    k_agg128<<<gA, 256>>>(hbuf, mb0, bufA, Abuf, N, 0);
    k_in_stats<<<512, 128>>>(bufA, N);
    k_in_apply_half<<<(N * HID + 255) / 256, 256>>>(bufA, N);
    for (int l = 0; l < 8; ++l) {
        k_mmagemm<<<gMM, 256, GEMM_SMEM>>>(Abuf,
            Bbuf + (size_t)(1 + l) * SLOT_ELEMS, hbuf, N, 128, 1);
        k_agg128<<<gA, 256>>>(hbuf, mbh + (size_t)l * HID, bufA, Abuf, N, l < 7 ? 1 : 2);
    }
    k_mmagemm<<<gMM, 256, GEMM_SMEM>>>(Abuf,
        Bbuf + (size_t)9 * SLOT_ELEMS, hbuf, N, 128, 1);
    k_agg128<<<gA, 256>>>(hbuf, mb9, bufA, Abuf, N, 3);   // tanh -> mesh fp16

    // ---- precompute M0 = mesh @ dW0[4:132]  (time-invariant, fp32) ----
    k_mmagemm<<<gMM, 256, GEMM_SMEM>>>(Abuf,
        Bbuf + (size_t)18 * SLOT_ELEMS, M0buf, N, 128, 0);

    // ---- time stepping ----
    k_copyF0<<<gN, 256>>>(F0, N);
    k_conv0_diff<<<gA, 256>>>(dW0, N);   // h for t=0; later steps come from k_step_fused
    for (int t = 0; t < T; ++t) {
        k_agg128<<<gA, 256>>>(hbuf, db0, bufA, Abuf, N, 0);   // also zeroes stats
        k_in_stats<<<512, 128>>>(bufA, N);
        k_in_apply_half<<<(N * HID + 255) / 256, 256>>>(bufA, N);
        for (int l = 0; l < 8; ++l) {
            k_mmagemm<<<gMM, 256, GEMM_SMEM>>>(Abuf,
                Bbuf + (size_t)(10 + l) * SLOT_ELEMS, hbuf, N, 128, 1);
            if (l < 7)
                k_agg128<<<gA, 256>>>(hbuf, dbh + (size_t)l * HID, bufA, Abuf, N, 1);
        }
        k_agg_h4<<<gA, 256>>>(hbuf, dbh + (size_t)7 * HID, dW9, h4, N);
        k_step_fused<<<gA, 256>>>(h4, db9, dW0, out, N, T, t);
    }
}

// round 15
// speedup vs baseline: 1.3776x; 1.0337x over previous
#include <cuda_runtime.h>
#include <cuda_fp16.h>
#include <math.h>
#include <stdint.h>

// Problem constants (fixed for this dataset)
#define MAXN 30000
#define MAXE 480000
#define MAXNE (MAXE + MAXN)
#define HID 128
#define EPSV 1e-5f
#define DTV 0.1f
#define NSLOT 19
#define SLOT_ELEMS (128 * 128)

// ---------------- scratch (static device memory; no runtime allocs) ----------
__device__ int   g_deg[MAXN];
__device__ float g_dinv[MAXN];
__device__ int   g_rp[MAXN + 1];
__device__ int   g_cur[MAXN];
__device__ int   g_csrc[MAXNE];
__device__ float g_cw[MAXNE];
__device__ float g_stats[2 * HID];
__device__ int   g_lex[MAXN];
__device__ int   g_bsum[256];

__device__ __align__(16) __half g_h[(size_t)MAXN * HID];    // GEMM output (pre-aggregation), fp16
__device__ __align__(16) float g_bufA[(size_t)MAXN * HID];  // fp32 activations (IN input)
__device__ __align__(16) float g_M0[(size_t)MAXN * HID];    // precomputed mesh @ W0[4:132]
__device__ __align__(16) float g_F[MAXN * 4];
__device__ __align__(16) float g_h4[MAXN * 4];

// fp16 GEMM operand buffers
__device__ __align__(16) __half g_A[(size_t)MAXN * HID];
__device__ __align__(16) __half g_B[NSLOT * SLOT_ELEMS];

// ---------------- helpers -----------------------------------------------------
__device__ __forceinline__ uint32_t smem_u32(const void* p) {
    uint32_t a;
    asm("{ .reg .u64 t; cvta.to.shared.u64 t, %1; cvt.u32.u64 %0, t; }" : "=r"(a) : "l"(p));
    return a;
}

__device__ __forceinline__ void ldmx4(uint32_t* r, uint32_t addr) {
    asm volatile("ldmatrix.sync.aligned.m8n8.x4.shared.b16 {%0,%1,%2,%3}, [%4];"
                 : "=r"(r[0]), "=r"(r[1]), "=r"(r[2]), "=r"(r[3]) : "r"(addr));
}

__device__ __forceinline__ void mma16816(float* c, const uint32_t* a, uint32_t b0, uint32_t b1) {
    asm volatile("mma.sync.aligned.m16n8k16.row.col.f32.f16.f16.f32 "
                 "{%0,%1,%2,%3}, {%4,%5,%6,%7}, {%8,%9}, {%0,%1,%2,%3};"
                 : "+f"(c[0]), "+f"(c[1]), "+f"(c[2]), "+f"(c[3])
                 : "r"(a[0]), "r"(a[1]), "r"(a[2]), "r"(a[3]), "r"(b0), "r"(b1));
}

__device__ __forceinline__ void half_store4(float4 v, __half* p) {
    __half2 h01 = __floats2half2_rn(v.x, v.y);
    __half2 h23 = __floats2half2_rn(v.z, v.w);
    uint2 pk;
    pk.x = *(uint32_t*)&h01; pk.y = *(uint32_t*)&h23;
    *(uint2*)p = pk;
}

__device__ __forceinline__ void acc_row(float4& acc, uint2 raw, float w) {
    float2 f01 = __half22float2(*(__half2*)&raw.x);
    float2 f23 = __half22float2(*(__half2*)&raw.y);
    acc.x += w * f01.x; acc.y += w * f01.y;
    acc.z += w * f23.x; acc.w += w * f23.y;
}

// ---------------- graph preprocessing ----------------------------------------
__global__ void k_init_deg(int n) {
    int i = blockIdx.x * blockDim.x + threadIdx.x;
    if (i < n) g_deg[i] = 1;  // self-loop
}

__global__ void k_count(const int* __restrict__ ei, int E) {
    int e = blockIdx.x * blockDim.x + threadIdx.x;
    if (e < E) atomicAdd(&g_deg[ei[E + e]], 1);
}

__global__ void k_dinv(int n) {
    int i = blockIdx.x * blockDim.x + threadIdx.x;
    if (i < n) g_dinv[i] = rsqrtf((float)g_deg[i]);
}

// multi-block exclusive scan: scan1 (local) -> scan2 (block sums) -> scan3 (add)
__global__ void k_scan1(int n) {
    __shared__ int ws[8];
    int b = blockIdx.x, t = threadIdx.x;
    int i = b * 256 + t;
    int lane = t & 31, w = t >> 5;
    int v = (i < n) ? g_deg[i] : 0;
    int x = v;
    #pragma unroll
    for (int o = 1; o < 32; o <<= 1) {
        int t2 = __shfl_up_sync(0xFFFFFFFFu, x, o);
        if (lane >= o) x += t2;
    }
    if (lane == 31) ws[w] = x;
    __syncthreads();
    if (w == 0) {
        int s = (lane < 8) ? ws[lane] : 0;
        #pragma unroll
        for (int o = 1; o < 8; o <<= 1) {
            int t2 = __shfl_up_sync(0xFFFFFFFFu, s, o);
            if (lane >= o) s += t2;
        }
        if (lane < 8) ws[lane] = s;
    }
    __syncthreads();
    int woff = (w > 0) ? ws[w - 1] : 0;
    if (i < n) g_lex[i] = woff + x - v;
    if (t == 255) g_bsum[b] = woff + x;
}

__global__ void k_scan2(int nb, int n) {
    __shared__ int ws[8];
    int t = threadIdx.x;
    int lane = t & 31, w = t >> 5;
    int v = (t < nb) ? g_bsum[t] : 0;
    int x = v;
    #pragma unroll
    for (int o = 1; o < 32; o <<= 1) {
        int t2 = __shfl_up_sync(0xFFFFFFFFu, x, o);
        if (lane >= o) x += t2;
    }
    if (lane == 31) ws[w] = x;
    __syncthreads();
    if (w == 0) {
        int s = (lane < 8) ? ws[lane] : 0;
        #pragma unroll
        for (int o = 1; o < 8; o <<= 1) {
            int t2 = __shfl_up_sync(0xFFFFFFFFu, s, o);
            if (lane >= o) s += t2;
        }
        if (lane < 8) ws[lane] = s;
    }
    __syncthreads();
    int woff = (w > 0) ? ws[w - 1] : 0;
    int excl = woff + x - v;
    __syncthreads();
    if (t < nb) g_bsum[t] = excl;
    if (t == nb - 1) g_rp[n] = woff + x;
}

__global__ void k_scan3(int n) {
    int i = blockIdx.x * blockDim.x + threadIdx.x;
    if (i < n) {
        int v = g_lex[i] + g_bsum[i >> 8];
        g_rp[i] = v;
        g_cur[i] = v;
    }
}

__global__ void k_fill(const int* __restrict__ ei, int E, int n) {
    int idx = blockIdx.x * blockDim.x + threadIdx.x;
    if (idx < E) {
        int s = ei[idx], d = ei[E + idx];
        int pos = atomicAdd(&g_cur[d], 1);
        g_csrc[pos] = s;
        g_cw[pos] = g_dinv[s] * g_dinv[d];
    } else if (idx < E + n) {
        int i = idx - E;
        int pos = atomicAdd(&g_cur[i], 1);
        g_csrc[pos] = i;
        g_cw[pos] = g_dinv[i] * g_dinv[i];
    }
}

// ---------------- weight conversion: W[KxN] fp32 -> B[NxKpad] fp16 -----------
struct WTab {
    const float* src[NSLOT];
    int K[NSLOT];
    int Kp[NSLOT];
};

__global__ void k_wconv(WTab t) {
    int slot = blockIdx.y;
    int Kp = t.Kp[slot];
    int idx = blockIdx.x * 256 + threadIdx.x;
    if (idx >= 128 * Kp) return;
    int nrow = idx / Kp, k = idx % Kp;
    float v = (k < t.K[slot]) ? t.src[slot][(size_t)k * 128 + nrow] : 0.0f;
    g_B[slot * SLOT_ELEMS + idx] = __float2half(v);
}

// meshfield [Nx8] fp32 -> fp16 [Nx16] (cols 8..15 zero)
__global__ void k_meshin(const float* __restrict__ mf, int n) {
    int idx = blockIdx.x * blockDim.x + threadIdx.x;
    if (idx >= n * 16) return;
    int node = idx >> 4, c = idx & 15;
    float v = (c < 8) ? mf[node * 8 + c] : 0.0f;
    g_A[idx] = __float2half(v);
}

// ---------------- mma.sync fp16 GEMM, M-tile 128 ------------------------------
#define SMS 136                         // smem row stride in halves (128 + 8 pad)
#define SM_A 0
#define SM_B (128 * SMS * 2)            // 34816
#define GEMM_SMEM (SM_B + 128 * SMS * 2)  // 69632 bytes

__global__ __launch_bounds__(256) void k_mmagemm(
    const __half* __restrict__ A, const __half* __restrict__ B,
    void* __restrict__ outp, int n, int K, int out_half)
{
    extern __shared__ __align__(16) char smem[];
    int tid = threadIdx.x;
    int m0 = blockIdx.x * 128;
    int nb8 = K >> 3;

    for (int idx = tid; idx < 128 * nb8; idx += 256) {
        int r = idx / nb8, c = idx - r * nb8;
        uint4 v = *(const uint4*)(B + (size_t)r * K + c * 8);
        *(uint4*)(smem + SM_B + (r * SMS + c * 8) * 2) = v;
    }
    for (int idx = tid; idx < 128 * nb8; idx += 256) {
        int r = idx / nb8, c = idx - r * nb8;
        int gr = m0 + r;
        uint4 v = make_uint4(0, 0, 0, 0);
        if (gr < n) v = *(const uint4*)(A + (size_t)gr * K + c * 8);
        *(uint4*)(smem + SM_A + (r * SMS + c * 8) * 2) = v;
    }
    __syncthreads();

    uint32_t sb = smem_u32(smem);
    int wid = tid >> 5, lane = tid & 31;
    int rowbase = wid * 16;

    int a_row  = (lane & 7) + ((lane >> 3) & 1) * 8;
    int a_koff = (lane >> 4) * 8;
    int b_nrow = ((lane >> 4) * 8) + (lane & 7);
    int b_koff = ((lane >> 3) & 1) * 8;

    float acc[16][4];
    #pragma unroll
    for (int j = 0; j < 16; j++)
        #pragma unroll
        for (int q = 0; q < 4; q++) acc[j][q] = 0.f;

    int ksteps = K >> 4;
    for (int ks = 0; ks < ksteps; ks++) {
        uint32_t a0[4];
        uint32_t aaddr = sb + SM_A + (uint32_t)(((rowbase + a_row) * SMS + a_koff + ks * 16) * 2);
        ldmx4(a0, aaddr);
        #pragma unroll
        for (int p = 0; p < 8; p++) {
            uint32_t b[4];
            uint32_t baddr = sb + SM_B + (uint32_t)(((p * 16 + b_nrow) * SMS + b_koff + ks * 16) * 2);
            ldmx4(b, baddr);
            mma16816(acc[2 * p + 0], a0, b[0], b[1]);
            mma16816(acc[2 * p + 1], a0, b[2], b[3]);
        }
    }

    int g = lane >> 2, i4 = lane & 3;
    int r0 = m0 + rowbase + g;
    if (out_half) {
        __half* out = (__half*)outp;
        #pragma unroll
        for (int nt = 0; nt < 16; nt++) {
            int col = nt * 8 + i4 * 2;
            if (r0 < n)
                *(__half2*)(out + (size_t)r0 * 128 + col) =
                    __floats2half2_rn(acc[nt][0], acc[nt][1]);
            if (r0 + 8 < n)
                *(__half2*)(out + (size_t)(r0 + 8) * 128 + col) =
                    __floats2half2_rn(acc[nt][2], acc[nt][3]);
        }
    } else {
        float* out = (float*)outp;
        #pragma unroll
        for (int nt = 0; nt < 16; nt++) {
            int col = nt * 8 + i4 * 2;
            if (r0 < n)
                *(float2*)(out + (size_t)r0 * 128 + col) = make_float2(acc[nt][0], acc[nt][1]);
            if (r0 + 8 < n)
                *(float2*)(out + (size_t)(r0 + 8) * 128 + col) = make_float2(acc[nt][2], acc[nt][3]);
        }
    }
}

// ---------------- aggregation: out[d] = b + sum_e w_e * h[src_e] (128 ch) ----
// h is fp16 (256B rows). mode 0: fp32 out (+zero stats); 1: relu->fp16; 2: fp16; 3: tanh->fp16
__global__ __launch_bounds__(256) void k_agg128(
    const __half* __restrict__ h, const float* __restrict__ bias,
    float* __restrict__ outF, __half* __restrict__ outHalf,
    int n, int mode)
{
    if (mode == 0 && blockIdx.x == 0) g_stats[threadIdx.x] = 0.f;  // fold zero_stats
    int node = blockIdx.x * 8 + (threadIdx.x >> 5);
    if (node >= n) return;
    int lane = threadIdx.x & 31;
    float4 acc = ((const float4*)bias)[lane];
    int e = g_rp[node], e1 = g_rp[node + 1];
    for (; e + 8 <= e1; e += 8) {
        int s[8]; float w[8]; uint2 r[8];
        #pragma unroll
        for (int q = 0; q < 8; q++) { s[q] = g_csrc[e + q]; w[q] = g_cw[e + q]; }
        #pragma unroll
        for (int q = 0; q < 8; q++) r[q] = ((const uint2*)(h + (size_t)s[q] * 128))[lane];
        #pragma unroll
        for (int q = 0; q < 8; q++) acc_row(acc, r[q], w[q]);
    }
    for (; e + 4 <= e1; e += 4) {
        int s[4]; float w[4]; uint2 r[4];
        #pragma unroll
        for (int q = 0; q < 4; q++) { s[q] = g_csrc[e + q]; w[q] = g_cw[e + q]; }
        #pragma unroll
        for (int q = 0; q < 4; q++) r[q] = ((const uint2*)(h + (size_t)s[q] * 128))[lane];
        #pragma unroll
        for (int q = 0; q < 4; q++) acc_row(acc, r[q], w[q]);
    }
    for (; e < e1; ++e) {
        int s = g_csrc[e]; float w = g_cw[e];
        uint2 rv = ((const uint2*)(h + (size_t)s * 128))[lane];
        acc_row(acc, rv, w);
    }
    if (mode == 0) {
        ((float4*)(outF + (size_t)node * 128))[lane] = acc;
    } else {
        if (mode == 1) {
            acc.x = fmaxf(acc.x, 0.f); acc.y = fmaxf(acc.y, 0.f);
            acc.z = fmaxf(acc.z, 0.f); acc.w = fmaxf(acc.w, 0.f);
        } else if (mode == 3) {
            acc.x = tanhf(acc.x); acc.y = tanhf(acc.y);
            acc.z = tanhf(acc.z); acc.w = tanhf(acc.w);
        }
        half_store4(acc, outHalf + (size_t)node * 128 + lane * 4);
    }
}

// ---------------- FUSED final conv9 front-half: h4 = (agg(h)+b) @ W9 ----------
// Same gather as k_agg128 (warp per node, per-lane channel split), then the
// k_gemm_h4 dot in identical order. Removes the bufA round-trip + one launch.
__global__ __launch_bounds__(256) void k_agg_h4(
    const __half* __restrict__ h, const float* __restrict__ bias,
    const float* __restrict__ W9, float* __restrict__ h4, int n)
{
    int node = blockIdx.x * 8 + (threadIdx.x >> 5);
    if (node >= n) return;
    int lane = threadIdx.x & 31;
    float4 acc = ((const float4*)bias)[lane];
    int e = g_rp[node], e1 = g_rp[node + 1];
    for (; e + 8 <= e1; e += 8) {
        int s[8]; float w[8]; uint2 r[8];
        #pragma unroll
        for (int q = 0; q < 8; q++) { s[q] = g_csrc[e + q]; w[q] = g_cw[e + q]; }
        #pragma unroll
        for (int q = 0; q < 8; q++) r[q] = ((const uint2*)(h + (size_t)s[q] * 128))[lane];
        #pragma unroll
        for (int q = 0; q < 8; q++) acc_row(acc, r[q], w[q]);
    }
    for (; e + 4 <= e1; e += 4) {
        int s[4]; float w[4]; uint2 r[4];
        #pragma unroll
        for (int q = 0; q < 4; q++) { s[q] = g_csrc[e + q]; w[q] = g_cw[e + q]; }
        #pragma unroll
        for (int q = 0; q < 4; q++) r[q] = ((const uint2*)(h + (size_t)s[q] * 128))[lane];
        #pragma unroll
        for (int q = 0; q < 4; q++) acc_row(acc, r[q], w[q]);
    }
    for (; e < e1; ++e) {
        int s = g_csrc[e]; float w = g_cw[e];
        uint2 rv = ((const uint2*)(h + (size_t)s * 128))[lane];
        acc_row(acc, rv, w);
    }
    const float4* Wv = (const float4*)W9;
    float4 w0 = Wv[lane * 4 + 0], w1 = Wv[lane * 4 + 1];
    float4 w2 = Wv[lane * 4 + 2], w3 = Wv[lane * 4 + 3];
    float4 p;
    p.x = acc.x * w0.x + acc.y * w1.x + acc.z * w2.x + acc.w * w3.x;
    p.y = acc.x * w0.y + acc.y * w1.y + acc.z * w2.y + acc.w * w3.y;
    p.z = acc.x * w0.z + acc.y * w1.z + acc.z * w2.z + acc.w * w3.z;
    p.w = acc.x * w0.w + acc.y * w1.w + acc.z * w2.w + acc.w * w3.w;
    #pragma unroll
    for (int o = 16; o > 0; o >>= 1) {
        p.x += __shfl_xor_sync(0xFFFFFFFFu, p.x, o);
        p.y += __shfl_xor_sync(0xFFFFFFFFu, p.y, o);
        p.z += __shfl_xor_sync(0xFFFFFFFFu, p.z, o);
        p.w += __shfl_xor_sync(0xFFFFFFFFu, p.w, o);
    }
    if (lane == 0) ((float4*)h4)[node] = p;
}

// ---------------- instance norm ----------------------------------------------
__global__ __launch_bounds__(128) void k_in_stats(const float* __restrict__ x, int n) {
    int c = threadIdx.x;
    int chunk = (n + gridDim.x - 1) / gridDim.x;
    int r0 = blockIdx.x * chunk;
    int r1 = min(n, r0 + chunk);
    float s = 0.f, q = 0.f;
    for (int r = r0; r < r1; ++r) {
        float v = x[(size_t)r * HID + c];
        s += v; q += v * v;
    }
    atomicAdd(&g_stats[c], s);
    atomicAdd(&g_stats[HID + c], q);
}

// apply IN, then ReLU, write fp16 (feeds first middle conv)
__global__ void k_in_apply_half(const float* __restrict__ x, int n) {
    int idx = blockIdx.x * blockDim.x + threadIdx.x;
    if (idx >= n * HID) return;
    int c = idx & (HID - 1);
    float inv_n = 1.f / (float)n;
    float m = g_stats[c] * inv_n;
    float v = g_stats[HID + c] * inv_n - m * m;
    float y = (x[idx] - m) * rsqrtf(v + EPSV);
    y = fmaxf(y, 0.f);
    g_A[idx] = __float2half(y);
}

// ---------------- misc small kernels ------------------------------------------
__global__ void k_copyF0(const float* __restrict__ F0, int n) {
    int i = blockIdx.x * blockDim.x + threadIdx.x;
    if (i < n) ((float4*)g_F)[i] = ((const float4*)F0)[i];
}

// h = F @ W0[0:4] + M0   (diff conv0, mesh part precomputed), fp16 out
__global__ __launch_bounds__(256) void k_conv0_diff(const float* __restrict__ W0, int n) {
    int node = blockIdx.x * 8 + (threadIdx.x >> 5);
    if (node >= n) return;
    int lane = threadIdx.x & 31;
    float4 Fv = ((const float4*)g_F)[node];
    float4 m = ((const float4*)(g_M0 + (size_t)node * 128))[lane];
    const float4* w = (const float4*)W0;
    float4 w0 = w[0 * 32 + lane], w1 = w[1 * 32 + lane];
    float4 w2 = w[2 * 32 + lane], w3 = w[3 * 32 + lane];
    m.x += Fv.x * w0.x + Fv.y * w1.x + Fv.z * w2.x + Fv.w * w3.x;
    m.y += Fv.x * w0.y + Fv.y * w1.y + Fv.z * w2.y + Fv.w * w3.y;
    m.z += Fv.x * w0.z + Fv.y * w1.z + Fv.z * w2.z + Fv.w * w3.z;
    m.w += Fv.x * w0.w + Fv.y * w1.w + Fv.z * w2.w + Fv.w * w3.w;
    half_store4(m, g_h + (size_t)node * 128 + lane * 4);
}

// fused: 4-channel aggregation + bias + tanh -> F_dot; F update; write outputs
// (thread-per-node — maximal gather parallelism)
__global__ void k_agg4_step(const float* __restrict__ h4, const float* __restrict__ b,
                            float* __restrict__ out, int n, int T, int t)
{
    int i = blockIdx.x * blockDim.x + threadIdx.x;
    if (i >= n) return;
    float4 acc = *(const float4*)b;
    int e0 = g_rp[i], e1 = g_rp[i + 1];
    for (int e = e0; e < e1; ++e) {
        int s = g_csrc[e]; float w = g_cw[e];
        float4 hv = ((const float4*)h4)[s];
        acc.x += w * hv.x; acc.y += w * hv.y; acc.z += w * hv.z; acc.w += w * hv.w;
    }
    float4 fd;
    fd.x = tanhf(acc.x); fd.y = tanhf(acc.y);
    fd.z = tanhf(acc.z); fd.w = tanhf(acc.w);
    float4 fc = ((const float4*)g_F)[i];
    float4 fn;
    fn.x = tanhf(fc.x + fd.x * DTV);
    fn.y = tanhf(fc.y + fd.y * DTV);
    fn.z = tanhf(fc.z + fd.z * DTV);
    fn.w = tanhf(fc.w + fd.w * DTV);
    ((float4*)g_F)[i] = fn;
    float4* ob = (float4*)out;
    ob[(size_t)i * T + t] = fn;                     // Fs     [N][T][4]
    ob[(size_t)n * T + (size_t)i * T + t] = fd;     // F_dots [N][T][4]
}

// ---------------- host orchestration ------------------------------------------
extern "C" void kernel_launch(void* const* d_in, const int* in_sizes, int n_in,
                              void* d_out, int out_size)
{
    const float* F0    = (const float*)d_in[0];
    const int*   ei    = (const int*)d_in[1];
    const float* meshf = (const float*)d_in[2];
    const float* mW0   = (const float*)d_in[4];
    const float* mb0   = (const float*)d_in[5];
    const float* mWh   = (const float*)d_in[6];
    const float* mbh   = (const float*)d_in[7];
    const float* mW9   = (const float*)d_in[8];
    const float* mb9   = (const float*)d_in[9];
    const float* dW0   = (const float*)d_in[10];
    const float* db0   = (const float*)d_in[11];
    const float* dWh   = (const float*)d_in[12];
    const float* dbh   = (const float*)d_in[13];
    const float* dW9   = (const float*)d_in[14];
    const float* db9   = (const float*)d_in[15];
    float* out = (float*)d_out;

    int N = in_sizes[0] / 4;
    int E = in_sizes[1] / 2;
    int T = out_size / (2 * N * 4);
    if (N > MAXN || E > MAXE || T <= 0) return;

    float *bufA, *M0buf, *h4;
    __half *hbuf, *Abuf, *Bbuf;
    cudaGetSymbolAddress((void**)&hbuf,  g_h);
    cudaGetSymbolAddress((void**)&bufA,  g_bufA);
    cudaGetSymbolAddress((void**)&M0buf, g_M0);
    cudaGetSymbolAddress((void**)&h4,    g_h4);
    cudaGetSymbolAddress((void**)&Abuf,  g_A);
    cudaGetSymbolAddress((void**)&Bbuf,  g_B);

    cudaFuncSetAttribute(k_mmagemm, cudaFuncAttributeMaxDynamicSharedMemorySize, GEMM_SMEM);

    int gN = (N + 255) / 256;
    int gE = (E + 255) / 256;
    int gMM = (N + 127) / 128;   // GEMM M-tiles of 128
    int gA = (N + 7) / 8;
    int nb = (N + 255) / 256;

    // ---- graph preprocessing ----
    k_init_deg<<<gN, 256>>>(N);
    k_count<<<gE, 256>>>(ei, E);
    k_dinv<<<gN, 256>>>(N);
    k_scan1<<<nb, 256>>>(N);
    k_scan2<<<1, 256>>>(nb, N);
    k_scan3<<<gN, 256>>>(N);
    k_fill<<<(E + N + 255) / 256, 256>>>(ei, E, N);

    // ---- weight conversion (all 19 slots in one launch) ----
    WTab wt;
    wt.src[0] = mW0;  wt.K[0] = 8;   wt.Kp[0] = 16;            // mesh conv0
    for (int l = 0; l < 8; ++l) { wt.src[1 + l] = mWh + (size_t)l * HID * HID; wt.K[1 + l] = 128; wt.Kp[1 + l] = 128; }
    wt.src[9] = mW9;  wt.K[9] = 128; wt.Kp[9] = 128;           // mesh conv9
    for (int l = 0; l < 8; ++l) { wt.src[10 + l] = dWh + (size_t)l * HID * HID; wt.K[10 + l] = 128; wt.Kp[10 + l] = 128; }
    wt.src[18] = dW0 + 4 * HID; wt.K[18] = 128; wt.Kp[18] = 128;  // diff W0 mesh rows 4..131
    k_wconv<<<dim3(64, NSLOT), 256>>>(wt);

    // ---- mesh descriptor block ----
    k_meshin<<<(N * 16 + 255) / 256, 256>>>(meshf, N);
    k_mmagemm<<<gMM, 256, GEMM_SMEM>>>(Abuf, Bbuf, hbuf, N, 16, 1);
    k_agg128<<<gA, 256>>>(hbuf, mb0, bufA, Abuf, N, 0);
    k_in_stats<<<512, 128>>>(bufA, N);
    k_in_apply_half<<<(N * HID + 255) / 256, 256>>>(bufA, N);
    for (int l = 0; l < 8; ++l) {
        k_mmagemm<<<gMM, 256, GEMM_SMEM>>>(Abuf,
            Bbuf + (size_t)(1 + l) * SLOT_ELEMS, hbuf, N, 128, 1);
        k_agg128<<<gA, 256>>>(hbuf, mbh + (size_t)l * HID, bufA, Abuf, N, l < 7 ? 1 : 2);
    }
    k_mmagemm<<<gMM, 256, GEMM_SMEM>>>(Abuf,
        Bbuf + (size_t)9 * SLOT_ELEMS, hbuf, N, 128, 1);
    k_agg128<<<gA, 256>>>(hbuf, mb9, bufA, Abuf, N, 3);   // tanh -> mesh fp16

    // ---- precompute M0 = mesh @ dW0[4:132]  (time-invariant, fp32) ----
    k_mmagemm<<<gMM, 256, GEMM_SMEM>>>(Abuf,
        Bbuf + (size_t)18 * SLOT_ELEMS, M0buf, N, 128, 0);

    // ---- time stepping ----
    k_copyF0<<<gN, 256>>>(F0, N);
    for (int t = 0; t < T; ++t) {
        k_conv0_diff<<<gA, 256>>>(dW0, N);
        k_agg128<<<gA, 256>>>(hbuf, db0, bufA, Abuf, N, 0);   // also zeroes stats
        k_in_stats<<<512, 128>>>(bufA, N);
        k_in_apply_half<<<(N * HID + 255) / 256, 256>>>(bufA, N);
        for (int l = 0; l < 8; ++l) {
            k_mmagemm<<<gMM, 256, GEMM_SMEM>>>(Abuf,
                Bbuf + (size_t)(10 + l) * SLOT_ELEMS, hbuf, N, 128, 1);
            if (l < 7)
                k_agg128<<<gA, 256>>>(hbuf, dbh + (size_t)l * HID, bufA, Abuf, N, 1);
        }
        k_agg_h4<<<gA, 256>>>(hbuf, dbh + (size_t)7 * HID, dW9, h4, N);
        k_agg4_step<<<gN, 256>>>(h4, db9, out, N, T, t);
    }
}